// round 4
// baseline (speedup 1.0000x reference)
#include <cuda_runtime.h>
#include <cuda_fp16.h>
#include <math.h>
#include <stdint.h>

// ---------------- problem constants ----------------
#define SLEN 1024
#define BSZ  32
#define INDIM 512
#define H 8
#define D 64
#define NQKVB (H * (3 * D + 1))   // 1544
#define NQKVB_PAD 1664            // 13 * 128
#define MROWS (SLEN * BSZ)        // 32768
#define NBH   (BSZ * H)           // 256
#define LN_EPS 1e-5f

// ---------------- scratch ----------------
__device__ __half g_hh[(size_t)MROWS * INDIM];         // LN output, fp16
__device__ float  g_qkvb[(size_t)MROWS * NQKVB];       // GEMM1 out, fp32
__device__ float  g_q[(size_t)NBH * SLEN * D];
__device__ float  g_k[(size_t)NBH * SLEN * D];
__device__ float  g_v[(size_t)NBH * SLEN * D];
__device__ float  g_beta[(size_t)NBH * SLEN];
__device__ __half g_oh[(size_t)MROWS * INDIM];         // scan output, fp16
__device__ __half g_wslowT[(size_t)NQKVB_PAD * INDIM]; // [n][k] fp16, pad rows zero
__device__ __half g_woutT[(size_t)INDIM * INDIM];      // [n][k] fp16

// ---------------- transpose + fp16 convert (+zero-pad rows) ----------------
__global__ __launch_bounds__(256)
void transpose_pad_kernel(const float* __restrict__ src, __half* __restrict__ dst,
                          int K, int N, int Npad)
{
    __shared__ float tile[32][33];
    const int n0 = blockIdx.x * 32, k0 = blockIdx.y * 32;
    const int tx = threadIdx.x & 31, ty = threadIdx.x >> 5;  // 32 x 8
    #pragma unroll
    for (int i = ty; i < 32; i += 8) {
        const int n = n0 + tx;
        tile[i][tx] = (n < N) ? src[(size_t)(k0 + i) * N + n] : 0.f;
    }
    __syncthreads();
    #pragma unroll
    for (int i = ty; i < 32; i += 8) {
        const int n = n0 + i;
        if (n < Npad) dst[(size_t)n * K + k0 + tx] = __float2half(tile[tx][i]);
    }
}

// ---------------- LayerNorm -> fp16 ----------------
__global__ __launch_bounds__(256)
void ln_kernel(const float* __restrict__ x, const float* __restrict__ gamma,
               const float* __restrict__ beta)
{
    __shared__ float red[16];
    const int r = blockIdx.x;
    const int tid = threadIdx.x;
    const float* xr = x + (size_t)r * INDIM;
    float v0 = xr[tid];
    float v1 = xr[tid + 256];
    float s = v0 + v1;
    float ss = v0 * v0 + v1 * v1;
    #pragma unroll
    for (int o = 16; o; o >>= 1) {
        s  += __shfl_xor_sync(0xFFFFFFFFu, s, o);
        ss += __shfl_xor_sync(0xFFFFFFFFu, ss, o);
    }
    if ((tid & 31) == 0) { red[tid >> 5] = s; red[8 + (tid >> 5)] = ss; }
    __syncthreads();
    float st = 0.f, sst = 0.f;
    #pragma unroll
    for (int i = 0; i < 8; i++) { st += red[i]; sst += red[8 + i]; }
    const float mu  = st * (1.0f / INDIM);
    const float var = sst * (1.0f / INDIM) - mu * mu;
    const float inv = rsqrtf(var + LN_EPS);
    __half* hr = g_hh + (size_t)r * INDIM;
    hr[tid]       = __float2half((v0 - mu) * inv * gamma[tid]       + beta[tid]);
    hr[tid + 256] = __float2half((v1 - mu) * inv * gamma[tid + 256] + beta[tid + 256]);
}

// ---------------- fp16 mma.sync GEMM ----------------
// C[M,Ncols] = A[M,512](fp16) @ Bt[n][k](fp16)^T (+Res fp32)
// CTA tile 128x128, BK=32, 3-stage cp.async pipeline, 8 warps (2m x 4n), warp tile 64x32.
#define BK 32
#define KT (INDIM / BK)          // 16
#define ROWP 40                  // padded row stride in halfs (80B, 16B-aligned, conflict-free)
#define STAGE_HALFS (128 * ROWP) // 5120 halfs = 10240 B
#define GEMM_SMEM (3 * 2 * STAGE_HALFS * 2)  // 61440 B

__device__ __forceinline__ void load_stage(__half* sm, const __half* __restrict__ g,
                                           int row0, int k0, int tid)
{
    #pragma unroll
    for (int i = 0; i < 2; i++) {
        const int idx = tid + i * 256;
        const int row = idx >> 2;
        const int ch  = (idx & 3) << 3;           // 0,8,16,24 halfs
        const __half* gp = g + (size_t)(row0 + row) * INDIM + (k0 + ch);
        uint32_t dst;
        asm("{ .reg .u64 t; cvta.to.shared.u64 t, %1; cvt.u32.u64 %0, t; }"
            : "=r"(dst) : "l"(sm + row * ROWP + ch));
        asm volatile("cp.async.cg.shared.global [%0], [%1], 16;" :: "r"(dst), "l"(gp));
    }
}

__global__ __launch_bounds__(256)
void gemm_hmma_kernel(const __half* __restrict__ A, const __half* __restrict__ Bt,
                      float* __restrict__ C, const float* __restrict__ Res, int Ncols)
{
    extern __shared__ __half sm[];
    __half* SA = sm;                       // 3 stages
    __half* SB = sm + 3 * STAGE_HALFS;     // 3 stages

    const int tid = threadIdx.x, wid = tid >> 5, lane = tid & 31;
    const int bm = blockIdx.y * 128, bn = blockIdx.x * 128;
    const int wm = (wid >> 2) * 64;        // 0 or 64
    const int wn = (wid & 3) * 32;         // 0,32,64,96
    const int g = lane >> 2, c = lane & 3;

    float acc[4][4][4];
    #pragma unroll
    for (int i = 0; i < 4; i++)
        #pragma unroll
        for (int j = 0; j < 4; j++)
            #pragma unroll
            for (int r = 0; r < 4; r++) acc[i][j][r] = 0.f;

    // prologue: stages 0,1
    load_stage(SA, A, bm, 0, tid);
    load_stage(SB, Bt, bn, 0, tid);
    asm volatile("cp.async.commit_group;");
    load_stage(SA + STAGE_HALFS, A, bm, BK, tid);
    load_stage(SB + STAGE_HALFS, Bt, bn, BK, tid);
    asm volatile("cp.async.commit_group;");

    for (int kt = 0; kt < KT; ++kt) {
        asm volatile("cp.async.wait_group 1;");
        __syncthreads();
        // prefetch stage kt+2 into slot (kt+2)%3 (safe: all warps done with kt-1's slot)
        if (kt + 2 < KT) {
            const int ps = (kt + 2) % 3;
            load_stage(SA + ps * STAGE_HALFS, A, bm, (kt + 2) * BK, tid);
            load_stage(SB + ps * STAGE_HALFS, Bt, bn, (kt + 2) * BK, tid);
        }
        asm volatile("cp.async.commit_group;");

        const __half* sa = SA + (kt % 3) * STAGE_HALFS;
        const __half* sb = SB + (kt % 3) * STAGE_HALFS;
        #pragma unroll
        for (int ks = 0; ks < 2; ks++) {
            const int kb = ks * 16;
            uint32_t af[4][4], bf[4][2];
            #pragma unroll
            for (int im = 0; im < 4; im++) {
                const __half* p = sa + (wm + im * 16 + g) * ROWP + kb + 2 * c;
                af[im][0] = *(const uint32_t*)p;
                af[im][1] = *(const uint32_t*)(p + 8 * ROWP);
                af[im][2] = *(const uint32_t*)(p + 8);
                af[im][3] = *(const uint32_t*)(p + 8 * ROWP + 8);
            }
            #pragma unroll
            for (int in = 0; in < 4; in++) {
                const __half* p = sb + (wn + in * 8 + g) * ROWP + kb + 2 * c;
                bf[in][0] = *(const uint32_t*)p;
                bf[in][1] = *(const uint32_t*)(p + 8);
            }
            #pragma unroll
            for (int im = 0; im < 4; im++)
                #pragma unroll
                for (int in = 0; in < 4; in++)
                    asm volatile(
                        "mma.sync.aligned.m16n8k16.row.col.f32.f16.f16.f32 "
                        "{%0,%1,%2,%3}, {%4,%5,%6,%7}, {%8,%9}, {%0,%1,%2,%3};"
                        : "+f"(acc[im][in][0]), "+f"(acc[im][in][1]),
                          "+f"(acc[im][in][2]), "+f"(acc[im][in][3])
                        : "r"(af[im][0]), "r"(af[im][1]), "r"(af[im][2]), "r"(af[im][3]),
                          "r"(bf[in][0]), "r"(bf[in][1]));
        }
    }

    // epilogue
    #pragma unroll
    for (int im = 0; im < 4; im++) {
        #pragma unroll
        for (int in = 0; in < 4; in++) {
            const int col = bn + wn + in * 8 + 2 * c;
            if (col < Ncols) {
                const int r0 = bm + wm + im * 16 + g;
                float2 v0 = make_float2(acc[im][in][0], acc[im][in][1]);
                float2 v1 = make_float2(acc[im][in][2], acc[im][in][3]);
                if (Res) {
                    const float2 a0 = *(const float2*)(Res + (size_t)r0 * Ncols + col);
                    const float2 a1 = *(const float2*)(Res + (size_t)(r0 + 8) * Ncols + col);
                    v0.x += a0.x; v0.y += a0.y; v1.x += a1.x; v1.y += a1.y;
                }
                *(float2*)(C + (size_t)r0 * Ncols + col) = v0;
                *(float2*)(C + (size_t)(r0 + 8) * Ncols + col) = v1;
            }
        }
    }
}

// ---------------- activation + relayout ----------------
__device__ __forceinline__ float elu_p1(float x) {
    return x > 0.f ? x + 1.0f : expf(x);
}

__global__ __launch_bounds__(256)
void act_kernel()
{
    const int r = blockIdx.x;
    const int w = threadIdx.x >> 5;
    const int lane = threadIdx.x & 31;
    const int t = r >> 5, b = r & 31;
    const int bh = b * H + w;
    const float* p = g_qkvb + (size_t)r * NQKVB + w * (3 * D + 1);
    const size_t ob = ((size_t)bh * SLEN + t) * D;

    float q0 = elu_p1(p[lane]);
    float q1 = elu_p1(p[lane + 32]);
    float s = q0 + q1;
    #pragma unroll
    for (int o = 16; o; o >>= 1) s += __shfl_xor_sync(0xFFFFFFFFu, s, o);
    float inv = 1.0f / s;
    g_q[ob + lane] = q0 * inv;
    g_q[ob + lane + 32] = q1 * inv;

    float k0 = elu_p1(p[D + lane]);
    float k1 = elu_p1(p[D + lane + 32]);
    s = k0 + k1;
    #pragma unroll
    for (int o = 16; o; o >>= 1) s += __shfl_xor_sync(0xFFFFFFFFu, s, o);
    inv = 1.0f / s;
    g_k[ob + lane] = k0 * inv;
    g_k[ob + lane + 32] = k1 * inv;

    g_v[ob + lane] = p[2 * D + lane];
    g_v[ob + lane + 32] = p[2 * D + lane + 32];

    if (lane == 0)
        g_beta[(size_t)bh * SLEN + t] = 1.0f / (1.0f + expf(-p[3 * D]));
}

// ---------------- delta-rule scan (pipelined, 1 barrier/step) ----------------
__global__ __launch_bounds__(256)
void scan_kernel()
{
    const int bh = blockIdx.x;
    const int b = bh >> 3, h = bh & 7;
    const int tid = threadIdx.x;
    const int row = tid >> 2;
    const int c0 = (tid & 3) << 4;

    __shared__ float sk[2][D], sv[2][D], sq[2][D];
    __shared__ float sbet[2];

    const size_t base0 = (size_t)bh * SLEN * D;
    const int role = tid >> 6;       // 0:k 1:v 2:q 3:(beta on tid==192)
    const int rl = tid & 63;

    // fill buffer 0 with t=0; preA holds t=1
    float preA = 0.f;
    if (role == 0) { sk[0][rl] = g_k[base0 + rl]; preA = g_k[base0 + D + rl]; }
    else if (role == 1) { sv[0][rl] = g_v[base0 + rl]; preA = g_v[base0 + D + rl]; }
    else if (role == 2) { sq[0][rl] = g_q[base0 + rl]; preA = g_q[base0 + D + rl]; }
    else if (tid == 192) { sbet[0] = g_beta[(size_t)bh * SLEN]; preA = g_beta[(size_t)bh * SLEN + 1]; }
    __syncthreads();

    float W[16];
    #pragma unroll
    for (int j = 0; j < 16; j++) W[j] = 0.f;

    for (int t = 0; t < SLEN; t++) {
        const int cur = t & 1, nxt = cur ^ 1;

        // prefetch t+2 into regs (consumed at end of next iter -> ~1.5 iters of cover)
        float preB = 0.f;
        if (t + 2 < SLEN) {
            const size_t base2 = base0 + (size_t)(t + 2) * D;
            if (role == 0) preB = g_k[base2 + rl];
            else if (role == 1) preB = g_v[base2 + rl];
            else if (role == 2) preB = g_q[base2 + rl];
            else if (tid == 192) preB = g_beta[(size_t)bh * SLEN + t + 2];
        }

        const float bt = sbet[cur];
        float kk[16], qq[16];
        #pragma unroll
        for (int j4 = 0; j4 < 4; j4++) {
            *(float4*)&kk[j4 * 4] = *(const float4*)&sk[cur][c0 + j4 * 4];
            *(float4*)&qq[j4 * 4] = *(const float4*)&sq[cur][c0 + j4 * 4];
        }

        float vold = 0.f;
        #pragma unroll
        for (int j = 0; j < 16; j++) vold += W[j] * kk[j];
        vold += __shfl_xor_sync(0xFFFFFFFFu, vold, 1);
        vold += __shfl_xor_sync(0xFFFFFFFFu, vold, 2);

        const float upd = bt * (sv[cur][row] - vold);

        float op = 0.f;
        #pragma unroll
        for (int j = 0; j < 16; j++) {
            W[j] += upd * kk[j];
            op += W[j] * qq[j];
        }
        op += __shfl_xor_sync(0xFFFFFFFFu, op, 1);
        op += __shfl_xor_sync(0xFFFFFFFFu, op, 2);

        if ((tid & 3) == 0)
            g_oh[((size_t)(t * BSZ + b)) * INDIM + h * D + row] = __float2half(op);

        // publish t+1 into the other buffer
        if (t + 1 < SLEN) {
            if (role == 0) sk[nxt][rl] = preA;
            else if (role == 1) sv[nxt][rl] = preA;
            else if (role == 2) sq[nxt][rl] = preA;
            else if (tid == 192) sbet[nxt] = preA;
        }
        __syncthreads();
        preA = preB;
    }
}

// ---------------- launch ----------------
extern "C" void kernel_launch(void* const* d_in, const int* in_sizes, int n_in,
                              void* d_out, int out_size)
{
    const float* x      = (const float*)d_in[0];
    const float* gamma  = (const float*)d_in[1];
    const float* beta   = (const float*)d_in[2];
    const float* w_slow = (const float*)d_in[3];
    const float* w_out  = (const float*)d_in[4];
    float* out = (float*)d_out;

    static bool attr_set = false;
    if (!attr_set) {
        cudaFuncSetAttribute(gemm_hmma_kernel, cudaFuncAttributeMaxDynamicSharedMemorySize, GEMM_SMEM);
        attr_set = true;
    }

    __half* wslowT; cudaGetSymbolAddress((void**)&wslowT, g_wslowT);
    __half* woutT;  cudaGetSymbolAddress((void**)&woutT,  g_woutT);
    __half* hbuf;   cudaGetSymbolAddress((void**)&hbuf,   g_hh);
    float*  qkvb;   cudaGetSymbolAddress((void**)&qkvb,   g_qkvb);
    __half* obuf;   cudaGetSymbolAddress((void**)&obuf,   g_oh);

    // 0) weight transposes (n-major fp16 B)
    {
        dim3 blk(256);
        dim3 g1(NQKVB_PAD / 32, INDIM / 32);
        transpose_pad_kernel<<<g1, blk>>>(w_slow, wslowT, INDIM, NQKVB, NQKVB_PAD);
        dim3 g2(INDIM / 32, INDIM / 32);
        transpose_pad_kernel<<<g2, blk>>>(w_out, woutT, INDIM, INDIM, INDIM);
    }

    // 1) LayerNorm
    ln_kernel<<<MROWS, 256>>>(x, gamma, beta);

    // 2) qkvb = h @ w_slow
    {
        dim3 grid(NQKVB_PAD / 128, MROWS / 128);
        gemm_hmma_kernel<<<grid, 256, GEMM_SMEM>>>(hbuf, wslowT, qkvb, nullptr, NQKVB);
    }

    // 3) activations + relayout
    act_kernel<<<MROWS, 256>>>();

    // 4) delta-rule scan
    scan_kernel<<<NBH, 256>>>();

    // 5) out = x + o @ w_out
    {
        dim3 grid(INDIM / 128, MROWS / 128);
        gemm_hmma_kernel<<<grid, 256, GEMM_SMEM>>>(obuf, woutT, out, x, INDIM);
    }
}

// round 5
// speedup vs baseline: 1.3045x; 1.3045x over previous
#include <cuda_runtime.h>
#include <cuda_fp16.h>
#include <math.h>
#include <stdint.h>

#define SLEN 1024
#define BSZ  32
#define INDIM 512
#define H 8
#define D 64
#define NQKVB 1544
#define NQKVB_PAD 1664
#define MROWS 32768
#define NBH 256
#define NC 16
#define NCHUNKS (NBH * NC)
#define LN_EPS 1e-5f
#define PADH 72
#define PADF 65
#define TILE_H 4608   // halfs per 64xPADH tile

__device__ __half g_hh[(size_t)MROWS * INDIM];
__device__ __half g_qkvbh[(size_t)MROWS * NQKVB];
__device__ __half g_oh[(size_t)MROWS * INDIM];
__device__ __half g_wslowT[(size_t)NQKVB_PAD * INDIM];
__device__ __half g_woutT[(size_t)INDIM * INDIM];
__device__ __half g_Qc[(size_t)NCHUNKS * 4096];
__device__ __half g_Ktc[(size_t)NCHUNKS * 4096];
__device__ __half g_Sc[(size_t)NCHUNKS * 4096];
__device__ __half g_Ec[(size_t)NCHUNKS * 4096];
__device__ __half g_U0c[(size_t)NCHUNKS * 4096];

#define MMA16816(d, a0, a1, a2, a3, b0, b1)                                   \
    asm volatile("mma.sync.aligned.m16n8k16.row.col.f32.f16.f16.f32 "         \
        "{%0,%1,%2,%3},{%4,%5,%6,%7},{%8,%9},{%0,%1,%2,%3};"                   \
        : "+f"((d)[0]), "+f"((d)[1]), "+f"((d)[2]), "+f"((d)[3])               \
        : "r"(a0), "r"(a1), "r"(a2), "r"(a3), "r"(b0), "r"(b1))

// acc[nf*4+q] += A[m0+..][k] * B[n0+..][k]^T over k=0..63 (tiles stride PADH)
__device__ __forceinline__ void wgemm64(const __half* At, const __half* Bt,
                                        float acc[16], int m0, int n0, int g, int cq)
{
    #pragma unroll
    for (int kb = 0; kb < 64; kb += 16) {
        uint32_t a0 = *(const uint32_t*)&At[(m0 + g) * PADH + kb + 2 * cq];
        uint32_t a1 = *(const uint32_t*)&At[(m0 + 8 + g) * PADH + kb + 2 * cq];
        uint32_t a2 = *(const uint32_t*)&At[(m0 + g) * PADH + kb + 8 + 2 * cq];
        uint32_t a3 = *(const uint32_t*)&At[(m0 + 8 + g) * PADH + kb + 8 + 2 * cq];
        #pragma unroll
        for (int nf = 0; nf < 4; nf++) {
            uint32_t b0 = *(const uint32_t*)&Bt[(n0 + nf * 8 + g) * PADH + kb + 2 * cq];
            uint32_t b1 = *(const uint32_t*)&Bt[(n0 + nf * 8 + g) * PADH + kb + 8 + 2 * cq];
            MMA16816(&acc[nf * 4], a0, a1, a2, a3, b0, b1);
        }
    }
}

#define CP_COMMIT() asm volatile("cp.async.commit_group;")
#define CP_WAIT(n)  asm volatile("cp.async.wait_group %0;" :: "n"(n))

__device__ __forceinline__ void cpa_tile(__half* dst, const __half* src, int tid)
{
    #pragma unroll
    for (int i = 0; i < 2; i++) {
        int ch = tid + i * 256;
        int row = ch >> 3, off = (ch & 7) << 3;
        uint32_t d;
        asm("{ .reg .u64 t; cvta.to.shared.u64 t, %1; cvt.u32.u64 %0, t; }"
            : "=r"(d) : "l"(dst + row * PADH + off));
        asm volatile("cp.async.cg.shared.global [%0], [%1], 16;"
                     :: "r"(d), "l"(src + row * 64 + off));
    }
}

// ---------------- weight transpose ----------------
__global__ __launch_bounds__(256)
void transpose_pad_kernel(const float* __restrict__ src, __half* __restrict__ dst,
                          int K, int N, int Npad)
{
    __shared__ float tile[32][33];
    const int n0 = blockIdx.x * 32, k0 = blockIdx.y * 32;
    const int tx = threadIdx.x & 31, ty = threadIdx.x >> 5;
    #pragma unroll
    for (int i = ty; i < 32; i += 8) {
        const int n = n0 + tx;
        tile[i][tx] = (n < N) ? src[(size_t)(k0 + i) * N + n] : 0.f;
    }
    __syncthreads();
    #pragma unroll
    for (int i = ty; i < 32; i += 8) {
        const int n = n0 + i;
        if (n < Npad) dst[(size_t)n * K + k0 + tx] = __float2half(tile[tx][i]);
    }
}

// ---------------- LayerNorm ----------------
__global__ __launch_bounds__(256)
void ln_kernel(const float* __restrict__ x, const float* __restrict__ gamma,
               const float* __restrict__ beta)
{
    __shared__ float red[16];
    const int r = blockIdx.x, tid = threadIdx.x;
    const float* xr = x + (size_t)r * INDIM;
    float v0 = xr[tid], v1 = xr[tid + 256];
    float s = v0 + v1, ss = v0 * v0 + v1 * v1;
    #pragma unroll
    for (int o = 16; o; o >>= 1) {
        s  += __shfl_xor_sync(~0u, s, o);
        ss += __shfl_xor_sync(~0u, ss, o);
    }
    if ((tid & 31) == 0) { red[tid >> 5] = s; red[8 + (tid >> 5)] = ss; }
    __syncthreads();
    float st = 0.f, sst = 0.f;
    #pragma unroll
    for (int i = 0; i < 8; i++) { st += red[i]; sst += red[8 + i]; }
    const float mu = st * (1.f / INDIM);
    const float inv = rsqrtf(sst * (1.f / INDIM) - mu * mu + LN_EPS);
    __half* hr = g_hh + (size_t)r * INDIM;
    hr[tid]       = __float2half((v0 - mu) * inv * gamma[tid] + beta[tid]);
    hr[tid + 256] = __float2half((v1 - mu) * inv * gamma[tid + 256] + beta[tid + 256]);
}

// ---------------- big GEMM (fp16 in, fp32/fp16 out) ----------------
#define BK 32
#define KT (INDIM / BK)
#define ROWP 40
#define STG (128 * ROWP)
#define GEMM_SMEM (3 * 2 * STG * 2)

__device__ __forceinline__ void load_stage(__half* sm, const __half* __restrict__ g,
                                           int row0, int k0, int tid)
{
    #pragma unroll
    for (int i = 0; i < 2; i++) {
        const int idx = tid + i * 256;
        const int row = idx >> 2, ch = (idx & 3) << 3;
        uint32_t dst;
        asm("{ .reg .u64 t; cvta.to.shared.u64 t, %1; cvt.u32.u64 %0, t; }"
            : "=r"(dst) : "l"(sm + row * ROWP + ch));
        asm volatile("cp.async.cg.shared.global [%0], [%1], 16;"
                     :: "r"(dst), "l"(g + (size_t)(row0 + row) * INDIM + (k0 + ch)));
    }
}

__global__ __launch_bounds__(256)
void gemm_hmma_kernel(const __half* __restrict__ A, const __half* __restrict__ Bt,
                      float* __restrict__ C, __half* __restrict__ Ch,
                      const float* __restrict__ Res, int Ncols)
{
    extern __shared__ __half sm[];
    __half* SA = sm;
    __half* SB = sm + 3 * STG;
    const int tid = threadIdx.x, wid = tid >> 5, lane = tid & 31;
    const int bm = blockIdx.y * 128, bn = blockIdx.x * 128;
    const int wm = (wid >> 2) * 64, wn = (wid & 3) * 32;
    const int g = lane >> 2, c = lane & 3;

    float acc[4][4][4];
    #pragma unroll
    for (int i = 0; i < 4; i++)
        #pragma unroll
        for (int j = 0; j < 4; j++)
            #pragma unroll
            for (int r = 0; r < 4; r++) acc[i][j][r] = 0.f;

    load_stage(SA, A, bm, 0, tid); load_stage(SB, Bt, bn, 0, tid); CP_COMMIT();
    load_stage(SA + STG, A, bm, BK, tid); load_stage(SB + STG, Bt, bn, BK, tid); CP_COMMIT();

    for (int kt = 0; kt < KT; ++kt) {
        CP_WAIT(1);
        __syncthreads();
        if (kt + 2 < KT) {
            const int ps = (kt + 2) % 3;
            load_stage(SA + ps * STG, A, bm, (kt + 2) * BK, tid);
            load_stage(SB + ps * STG, Bt, bn, (kt + 2) * BK, tid);
        }
        CP_COMMIT();
        const __half* sa = SA + (kt % 3) * STG;
        const __half* sb = SB + (kt % 3) * STG;
        #pragma unroll
        for (int ks = 0; ks < 2; ks++) {
            const int kb = ks * 16;
            uint32_t af[4][4], bf[4][2];
            #pragma unroll
            for (int im = 0; im < 4; im++) {
                const __half* p = sa + (wm + im * 16 + g) * ROWP + kb + 2 * c;
                af[im][0] = *(const uint32_t*)p;
                af[im][1] = *(const uint32_t*)(p + 8 * ROWP);
                af[im][2] = *(const uint32_t*)(p + 8);
                af[im][3] = *(const uint32_t*)(p + 8 * ROWP + 8);
            }
            #pragma unroll
            for (int in = 0; in < 4; in++) {
                const __half* p = sb + (wn + in * 8 + g) * ROWP + kb + 2 * c;
                bf[in][0] = *(const uint32_t*)p;
                bf[in][1] = *(const uint32_t*)(p + 8);
            }
            #pragma unroll
            for (int im = 0; im < 4; im++)
                #pragma unroll
                for (int in = 0; in < 4; in++)
                    MMA16816(acc[im][in], af[im][0], af[im][1], af[im][2], af[im][3],
                             bf[in][0], bf[in][1]);
        }
    }

    #pragma unroll
    for (int im = 0; im < 4; im++)
        #pragma unroll
        for (int in = 0; in < 4; in++) {
            const int col = bn + wn + in * 8 + 2 * c;
            if (col < Ncols) {
                const int r0 = bm + wm + im * 16 + g;
                if (Ch) {
                    *(__half2*)&Ch[(size_t)r0 * Ncols + col] =
                        __floats2half2_rn(acc[im][in][0], acc[im][in][1]);
                    *(__half2*)&Ch[(size_t)(r0 + 8) * Ncols + col] =
                        __floats2half2_rn(acc[im][in][2], acc[im][in][3]);
                } else {
                    float2 v0 = make_float2(acc[im][in][0], acc[im][in][1]);
                    float2 v1 = make_float2(acc[im][in][2], acc[im][in][3]);
                    const float2 a0 = *(const float2*)(Res + (size_t)r0 * Ncols + col);
                    const float2 a1 = *(const float2*)(Res + (size_t)(r0 + 8) * Ncols + col);
                    v0.x += a0.x; v0.y += a0.y; v1.x += a1.x; v1.y += a1.y;
                    *(float2*)(C + (size_t)r0 * Ncols + col) = v0;
                    *(float2*)(C + (size_t)(r0 + 8) * Ncols + col) = v1;
                }
            }
        }
}

// ---------------- chunk prep (parallel over 4096 chunks) ----------------
#define PREP_SMEM (5 * TILE_H * 2 + 2 * 64 * PADF * 4 + 256)

__global__ __launch_bounds__(256, 2)
void chunk_prep_kernel()
{
    extern __shared__ char smraw[];
    __half* sK  = (__half*)smraw;
    __half* sQ  = sK  + TILE_H;
    __half* sKt = sQ  + TILE_H;
    __half* sVt = sKt + TILE_H;
    __half* sG  = sVt + TILE_H;
    float*  sA  = (float*)(sG + TILE_H);
    float*  sM  = sA + 64 * PADF;
    float*  sbt = sM + 64 * PADF;

    const int bid = blockIdx.x;
    const int bh = bid >> 4, cch = bid & 15;
    const int b = bh >> 3, hh = bh & 7;
    const int tid = threadIdx.x, wid = tid >> 5, lane = tid & 31;
    const int g = lane >> 2, cq = lane & 3;
    const int tt = tid >> 2, qt = tid & 3;
    const int t0 = cch * 64;
    const size_t cbase = (size_t)bid * 4096;

    // activations from qkvb (fp16)
    {
        const __half* rowp = g_qkvbh + (size_t)((t0 + tt) * BSZ + b) * NQKVB + hh * (3 * D + 1);
        if (qt == 0) sbt[tt] = 1.f / (1.f + expf(-__half2float(rowp[3 * D])));
        float qv[16], kv[16];
        float sq = 0.f, sk_ = 0.f;
        #pragma unroll
        for (int i = 0; i < 16; i++) {
            float xq = __half2float(rowp[qt * 16 + i]);
            float xk = __half2float(rowp[D + qt * 16 + i]);
            qv[i] = xq > 0.f ? xq + 1.f : expf(xq);
            kv[i] = xk > 0.f ? xk + 1.f : expf(xk);
            sq += qv[i]; sk_ += kv[i];
        }
        sq  += __shfl_xor_sync(~0u, sq, 1);  sq  += __shfl_xor_sync(~0u, sq, 2);
        sk_ += __shfl_xor_sync(~0u, sk_, 1); sk_ += __shfl_xor_sync(~0u, sk_, 2);
        const float iq = 1.f / sq, ik = 1.f / sk_;
        #pragma unroll
        for (int i = 0; i < 16; i++) {
            const int col = qt * 16 + i;
            __half hq = __float2half(qv[i] * iq);
            __half hk = __float2half(kv[i] * ik);
            sQ[tt * PADH + col] = hq;
            sK[tt * PADH + col] = hk;
            sKt[col * PADH + tt] = hk;
            sVt[col * PADH + tt] = rowp[2 * D + col];
        }
    }
    __syncthreads();

    const int m0 = (wid & 3) * 16, n0 = (wid >> 2) * 32;

    // A = beta_t * stril(K K^T); S = tril_incl(Q K^T)
    {
        float aA[16], aS[16];
        #pragma unroll
        for (int i = 0; i < 16; i++) { aA[i] = 0.f; aS[i] = 0.f; }
        wgemm64(sK, sK, aA, m0, n0, g, cq);
        wgemm64(sQ, sK, aS, m0, n0, g, cq);
        #pragma unroll
        for (int nf = 0; nf < 4; nf++)
            #pragma unroll
            for (int q = 0; q < 4; q++) {
                const int t = m0 + g + ((q >> 1) << 3);
                const int s = n0 + nf * 8 + 2 * cq + (q & 1);
                sA[t * PADF + s] = (s < t) ? sbt[t] * aA[nf * 4 + q] : 0.f;
                g_Sc[cbase + t * 64 + s] = __float2half((s <= t) ? aS[nf * 4 + q] : 0.f);
            }
    }
    #pragma unroll
    for (int i = 0; i < 16; i++) {
        const int e = tid * 16 + i;
        const int t = e >> 6, s2 = e & 63;
        sM[t * PADF + s2] = (t == s2) ? 1.f : 0.f;
    }
    __syncthreads();

    // M = (I+A)^{-1} forward substitution
    {
        const int cc = tid & 63, rg = tid >> 6;
        for (int s = 0; s < 63; s++) {
            if (cc <= s) {
                const float ms = sM[s * PADF + cc];
                for (int t = s + 1 + rg; t < 64; t += 4)
                    sM[t * PADF + cc] -= sA[t * PADF + s] * ms;
            }
            __syncthreads();
        }
    }
    // G = M * diag(beta_s)
    #pragma unroll
    for (int i = 0; i < 16; i++) {
        const int e = tid * 16 + i;
        const int t = e >> 6, s2 = e & 63;
        sG[t * PADH + s2] = __float2half(sM[t * PADF + s2] * sbt[s2]);
    }
    __syncthreads();

    // E = G @ K ; U0 = G @ V
    {
        float aE[16], aU[16];
        #pragma unroll
        for (int i = 0; i < 16; i++) { aE[i] = 0.f; aU[i] = 0.f; }
        wgemm64(sG, sKt, aE, m0, n0, g, cq);
        wgemm64(sG, sVt, aU, m0, n0, g, cq);
        #pragma unroll
        for (int nf = 0; nf < 4; nf++)
            #pragma unroll
            for (int qq = 0; qq < 2; qq++) {
                const int t = m0 + g + qq * 8;
                const int col = n0 + nf * 8 + 2 * cq;
                *(__half2*)&g_Ec[cbase + t * 64 + col] =
                    __floats2half2_rn(aE[nf * 4 + qq * 2], aE[nf * 4 + qq * 2 + 1]);
                *(__half2*)&g_U0c[cbase + t * 64 + col] =
                    __floats2half2_rn(aU[nf * 4 + qq * 2], aU[nf * 4 + qq * 2 + 1]);
            }
    }
    // store Q, K^T
    {
        const int row = tid >> 2, seg = (tid & 3) * 16;
        const uint32_t* qs = (const uint32_t*)&sQ[row * PADH + seg];
        const uint32_t* ks = (const uint32_t*)&sKt[row * PADH + seg];
        uint32_t* qd = (uint32_t*)&g_Qc[cbase + row * 64 + seg];
        uint32_t* kd = (uint32_t*)&g_Ktc[cbase + row * 64 + seg];
        #pragma unroll
        for (int i = 0; i < 8; i++) { qd[i] = qs[i]; kd[i] = ks[i]; }
    }
}

// ---------------- sequential chunk scan (256 CTAs, 16 chunks) ----------------
#define SCAN_SMEM (10 * TILE_H * 2 + 64 * 68 * 4)

__global__ __launch_bounds__(256)
void chunk_scan_kernel()
{
    extern __shared__ char smraw[];
    __half* base = (__half*)smraw;
    __half* sEb[2]  = { base,              base + 3 * TILE_H };
    __half* sKtb[2] = { base + TILE_H,     base + 4 * TILE_H };
    __half* sU0b[2] = { base + 2 * TILE_H, base + 5 * TILE_H };
    __half* sQh = base + 6 * TILE_H;
    __half* sS  = base + 7 * TILE_H;
    __half* sWh = base + 8 * TILE_H;
    __half* sUt = base + 9 * TILE_H;
    float*  sW  = (float*)(base + 10 * TILE_H);

    const int bh = blockIdx.x;
    const int b = bh >> 3, hh = bh & 7;
    const int tid = threadIdx.x, wid = tid >> 5, lane = tid & 31;
    const int g = lane >> 2, cq = lane & 3;
    const int m0 = (wid & 3) * 16, n0 = (wid >> 2) * 32;

    #pragma unroll
    for (int i = 0; i < 16; i++) {
        const int e = tid * 16 + i;
        const int r = e >> 6, c2 = e & 63;
        sW[r * 68 + c2] = 0.f;
        sWh[r * PADH + c2] = __float2half(0.f);
    }

    const size_t sb0 = (size_t)bh * NC * 4096;
    cpa_tile(sEb[0],  g_Ec  + sb0, tid);
    cpa_tile(sKtb[0], g_Ktc + sb0, tid);
    cpa_tile(sU0b[0], g_U0c + sb0, tid);
    CP_COMMIT();
    cpa_tile(sQh, g_Qc + sb0, tid);
    cpa_tile(sS,  g_Sc + sb0, tid);
    CP_COMMIT();

    for (int cch = 0; cch < NC; cch++) {
        const int cur = cch & 1, nxt = cur ^ 1;
        CP_WAIT(1);                 // trio(c) ready
        __syncthreads();
        if (cch + 1 < NC) {
            const size_t sbn = sb0 + (size_t)(cch + 1) * 4096;
            cpa_tile(sEb[nxt],  g_Ec  + sbn, tid);
            cpa_tile(sKtb[nxt], g_Ktc + sbn, tid);
            cpa_tile(sU0b[nxt], g_U0c + sbn, tid);
        }
        CP_COMMIT();

        // G1: ua = E @ W^T
        float ua[16];
        #pragma unroll
        for (int i = 0; i < 16; i++) ua[i] = 0.f;
        wgemm64(sEb[cur], sWh, ua, m0, n0, g, cq);

        CP_WAIT(1);                 // QS(c) ready
        __syncthreads();

        // Ut[i][t] = U0[t][i] - ua[t][i]
        #pragma unroll
        for (int nf = 0; nf < 4; nf++)
            #pragma unroll
            for (int qq = 0; qq < 2; qq++) {
                const int t = m0 + g + qq * 8;
                const int col = n0 + nf * 8 + 2 * cq;
                const __half2 u0 = *(const __half2*)&sU0b[cur][t * PADH + col];
                sUt[col * PADH + t]       = __float2half(__half2float(u0.x) - ua[nf * 4 + qq * 2]);
                sUt[(col + 1) * PADH + t] = __float2half(__half2float(u0.y) - ua[nf * 4 + qq * 2 + 1]);
            }

        // G2a: oa = Q @ W^T
        float oa[16];
        #pragma unroll
        for (int i = 0; i < 16; i++) oa[i] = 0.f;
        wgemm64(sQh, sWh, oa, m0, n0, g, cq);
        __syncthreads();            // sUt complete; W^T reads complete

        // G2b: oa += S @ U
        wgemm64(sS, sUt, oa, m0, n0, g, cq);

        // write O chunk
        #pragma unroll
        for (int nf = 0; nf < 4; nf++)
            #pragma unroll
            for (int qq = 0; qq < 2; qq++) {
                const int t = m0 + g + qq * 8;
                const int col = n0 + nf * 8 + 2 * cq;
                const size_t orow = (size_t)((cch * 64 + t) * BSZ + b) * INDIM + hh * D + col;
                *(__half2*)&g_oh[orow] =
                    __floats2half2_rn(oa[nf * 4 + qq * 2], oa[nf * 4 + qq * 2 + 1]);
            }

        // W += U^T @ K
        float wa[16];
        #pragma unroll
        for (int i = 0; i < 16; i++) wa[i] = 0.f;
        wgemm64(sUt, sKtb[cur], wa, m0, n0, g, cq);
        #pragma unroll
        for (int nf = 0; nf < 4; nf++)
            #pragma unroll
            for (int q = 0; q < 4; q++) {
                const int i = m0 + g + ((q >> 1) << 3);
                const int j = n0 + nf * 8 + 2 * cq + (q & 1);
                const float w = sW[i * 68 + j] + wa[nf * 4 + q];
                sW[i * 68 + j] = w;
                sWh[i * PADH + j] = __float2half(w);
            }
        __syncthreads();            // sWh updated; sQh/sS reads done
        if (cch + 1 < NC) {
            const size_t sbn = sb0 + (size_t)(cch + 1) * 4096;
            cpa_tile(sQh, g_Qc + sbn, tid);
            cpa_tile(sS,  g_Sc + sbn, tid);
        }
        CP_COMMIT();
    }
}

// ---------------- launch ----------------
extern "C" void kernel_launch(void* const* d_in, const int* in_sizes, int n_in,
                              void* d_out, int out_size)
{
    const float* x      = (const float*)d_in[0];
    const float* gamma  = (const float*)d_in[1];
    const float* beta   = (const float*)d_in[2];
    const float* w_slow = (const float*)d_in[3];
    const float* w_out  = (const float*)d_in[4];
    float* out = (float*)d_out;

    static bool attr_set = false;
    if (!attr_set) {
        cudaFuncSetAttribute(gemm_hmma_kernel, cudaFuncAttributeMaxDynamicSharedMemorySize, GEMM_SMEM);
        cudaFuncSetAttribute(chunk_prep_kernel, cudaFuncAttributeMaxDynamicSharedMemorySize, PREP_SMEM);
        cudaFuncSetAttribute(chunk_scan_kernel, cudaFuncAttributeMaxDynamicSharedMemorySize, SCAN_SMEM);
        attr_set = true;
    }

    __half* wslowT; cudaGetSymbolAddress((void**)&wslowT, g_wslowT);
    __half* woutT;  cudaGetSymbolAddress((void**)&woutT,  g_woutT);
    __half* hbuf;   cudaGetSymbolAddress((void**)&hbuf,   g_hh);
    __half* qkvbh;  cudaGetSymbolAddress((void**)&qkvbh,  g_qkvbh);
    __half* obuf;   cudaGetSymbolAddress((void**)&obuf,   g_oh);

    {
        dim3 blk(256);
        dim3 g1(NQKVB_PAD / 32, INDIM / 32);
        transpose_pad_kernel<<<g1, blk>>>(w_slow, wslowT, INDIM, NQKVB, NQKVB_PAD);
        dim3 g2(INDIM / 32, INDIM / 32);
        transpose_pad_kernel<<<g2, blk>>>(w_out, woutT, INDIM, INDIM, INDIM);
    }
    ln_kernel<<<MROWS, 256>>>(x, gamma, beta);
    {
        dim3 grid(NQKVB_PAD / 128, MROWS / 128);
        gemm_hmma_kernel<<<grid, 256, GEMM_SMEM>>>(hbuf, wslowT, nullptr, qkvbh, nullptr, NQKVB);
    }
    chunk_prep_kernel<<<NCHUNKS, 256, PREP_SMEM>>>();
    chunk_scan_kernel<<<NBH, 256, SCAN_SMEM>>>();
    {
        dim3 grid(INDIM / 128, MROWS / 128);
        gemm_hmma_kernel<<<grid, 256, GEMM_SMEM>>>(obuf, woutT, out, nullptr, x, INDIM);
    }
}

// round 6
// speedup vs baseline: 1.6321x; 1.2512x over previous
#include <cuda_runtime.h>
#include <cuda_fp16.h>
#include <math.h>
#include <stdint.h>

#define SLEN 1024
#define BSZ  32
#define INDIM 512
#define H 8
#define D 64
#define NQKVB 1544
#define NQKVB_PAD 1664
#define MROWS 32768
#define NBH 256
#define NC 16
#define NCHUNKS (NBH * NC)
#define LN_EPS 1e-5f
#define PADH 72
#define PADF 65
#define TILE_H 4608   // halfs per 64xPADH tile

__device__ __half g_hh[(size_t)MROWS * INDIM];
__device__ __half g_qkvbh[(size_t)MROWS * NQKVB];
__device__ __half g_oh[(size_t)MROWS * INDIM];
__device__ __half g_wslowT[(size_t)NQKVB_PAD * INDIM];
__device__ __half g_woutT[(size_t)INDIM * INDIM];
__device__ __half g_Qc[(size_t)NCHUNKS * 4096];
__device__ __half g_Ktc[(size_t)NCHUNKS * 4096];
__device__ __half g_Sc[(size_t)NCHUNKS * 4096];
__device__ __half g_Ec[(size_t)NCHUNKS * 4096];
__device__ __half g_U0c[(size_t)NCHUNKS * 4096];

#define MMA16816(d, a0, a1, a2, a3, b0, b1)                                   \
    asm volatile("mma.sync.aligned.m16n8k16.row.col.f32.f16.f16.f32 "         \
        "{%0,%1,%2,%3},{%4,%5,%6,%7},{%8,%9},{%0,%1,%2,%3};"                   \
        : "+f"((d)[0]), "+f"((d)[1]), "+f"((d)[2]), "+f"((d)[3])               \
        : "r"(a0), "r"(a1), "r"(a2), "r"(a3), "r"(b0), "r"(b1))

__device__ __forceinline__ void wgemm64(const __half* At, const __half* Bt,
                                        float acc[16], int m0, int n0, int g, int cq)
{
    #pragma unroll
    for (int kb = 0; kb < 64; kb += 16) {
        uint32_t a0 = *(const uint32_t*)&At[(m0 + g) * PADH + kb + 2 * cq];
        uint32_t a1 = *(const uint32_t*)&At[(m0 + 8 + g) * PADH + kb + 2 * cq];
        uint32_t a2 = *(const uint32_t*)&At[(m0 + g) * PADH + kb + 8 + 2 * cq];
        uint32_t a3 = *(const uint32_t*)&At[(m0 + 8 + g) * PADH + kb + 8 + 2 * cq];
        #pragma unroll
        for (int nf = 0; nf < 4; nf++) {
            uint32_t b0 = *(const uint32_t*)&Bt[(n0 + nf * 8 + g) * PADH + kb + 2 * cq];
            uint32_t b1 = *(const uint32_t*)&Bt[(n0 + nf * 8 + g) * PADH + kb + 8 + 2 * cq];
            MMA16816(&acc[nf * 4], a0, a1, a2, a3, b0, b1);
        }
    }
}

#define CP_COMMIT() asm volatile("cp.async.commit_group;")
#define CP_WAIT(n)  asm volatile("cp.async.wait_group %0;" :: "n"(n))

__device__ __forceinline__ void cpa_tile(__half* dst, const __half* src, int tid)
{
    #pragma unroll
    for (int i = 0; i < 2; i++) {
        int ch = tid + i * 256;
        int row = ch >> 3, off = (ch & 7) << 3;
        uint32_t d;
        asm("{ .reg .u64 t; cvta.to.shared.u64 t, %1; cvt.u32.u64 %0, t; }"
            : "=r"(d) : "l"(dst + row * PADH + off));
        asm volatile("cp.async.cg.shared.global [%0], [%1], 16;"
                     :: "r"(d), "l"(src + row * 64 + off));
    }
}

// ---------------- weight transpose ----------------
__global__ __launch_bounds__(256)
void transpose_pad_kernel(const float* __restrict__ src, __half* __restrict__ dst,
                          int K, int N, int Npad)
{
    __shared__ float tile[32][33];
    const int n0 = blockIdx.x * 32, k0 = blockIdx.y * 32;
    const int tx = threadIdx.x & 31, ty = threadIdx.x >> 5;
    #pragma unroll
    for (int i = ty; i < 32; i += 8) {
        const int n = n0 + tx;
        tile[i][tx] = (n < N) ? src[(size_t)(k0 + i) * N + n] : 0.f;
    }
    __syncthreads();
    #pragma unroll
    for (int i = ty; i < 32; i += 8) {
        const int n = n0 + i;
        if (n < Npad) dst[(size_t)n * K + k0 + tx] = __float2half(tile[tx][i]);
    }
}

// ---------------- LayerNorm ----------------
__global__ __launch_bounds__(256)
void ln_kernel(const float* __restrict__ x, const float* __restrict__ gamma,
               const float* __restrict__ beta)
{
    __shared__ float red[16];
    const int r = blockIdx.x, tid = threadIdx.x;
    const float* xr = x + (size_t)r * INDIM;
    float v0 = xr[tid], v1 = xr[tid + 256];
    float s = v0 + v1, ss = v0 * v0 + v1 * v1;
    #pragma unroll
    for (int o = 16; o; o >>= 1) {
        s  += __shfl_xor_sync(~0u, s, o);
        ss += __shfl_xor_sync(~0u, ss, o);
    }
    if ((tid & 31) == 0) { red[tid >> 5] = s; red[8 + (tid >> 5)] = ss; }
    __syncthreads();
    float st = 0.f, sst = 0.f;
    #pragma unroll
    for (int i = 0; i < 8; i++) { st += red[i]; sst += red[8 + i]; }
    const float mu = st * (1.f / INDIM);
    const float inv = rsqrtf(sst * (1.f / INDIM) - mu * mu + LN_EPS);
    __half* hr = g_hh + (size_t)r * INDIM;
    hr[tid]       = __float2half((v0 - mu) * inv * gamma[tid] + beta[tid]);
    hr[tid + 256] = __float2half((v1 - mu) * inv * gamma[tid + 256] + beta[tid + 256]);
}

// ---------------- big GEMM ----------------
#define BK 32
#define KT (INDIM / BK)
#define ROWP 40
#define STG (128 * ROWP)
#define GEMM_SMEM (3 * 2 * STG * 2)

__device__ __forceinline__ void load_stage(__half* sm, const __half* __restrict__ g,
                                           int row0, int k0, int tid)
{
    #pragma unroll
    for (int i = 0; i < 2; i++) {
        const int idx = tid + i * 256;
        const int row = idx >> 2, ch = (idx & 3) << 3;
        uint32_t dst;
        asm("{ .reg .u64 t; cvta.to.shared.u64 t, %1; cvt.u32.u64 %0, t; }"
            : "=r"(dst) : "l"(sm + row * ROWP + ch));
        asm volatile("cp.async.cg.shared.global [%0], [%1], 16;"
                     :: "r"(dst), "l"(g + (size_t)(row0 + row) * INDIM + (k0 + ch)));
    }
}

__global__ __launch_bounds__(256)
void gemm_hmma_kernel(const __half* __restrict__ A, const __half* __restrict__ Bt,
                      float* __restrict__ C, __half* __restrict__ Ch,
                      const float* __restrict__ Res, int Ncols)
{
    extern __shared__ __half sm[];
    __half* SA = sm;
    __half* SB = sm + 3 * STG;
    const int tid = threadIdx.x, wid = tid >> 5, lane = tid & 31;
    const int bm = blockIdx.y * 128, bn = blockIdx.x * 128;
    const int wm = (wid >> 2) * 64, wn = (wid & 3) * 32;
    const int g = lane >> 2, c = lane & 3;

    float acc[4][4][4];
    #pragma unroll
    for (int i = 0; i < 4; i++)
        #pragma unroll
        for (int j = 0; j < 4; j++)
            #pragma unroll
            for (int r = 0; r < 4; r++) acc[i][j][r] = 0.f;

    load_stage(SA, A, bm, 0, tid); load_stage(SB, Bt, bn, 0, tid); CP_COMMIT();
    load_stage(SA + STG, A, bm, BK, tid); load_stage(SB + STG, Bt, bn, BK, tid); CP_COMMIT();

    for (int kt = 0; kt < KT; ++kt) {
        CP_WAIT(1);
        __syncthreads();
        if (kt + 2 < KT) {
            const int ps = (kt + 2) % 3;
            load_stage(SA + ps * STG, A, bm, (kt + 2) * BK, tid);
            load_stage(SB + ps * STG, Bt, bn, (kt + 2) * BK, tid);
        }
        CP_COMMIT();
        const __half* sa = SA + (kt % 3) * STG;
        const __half* sb = SB + (kt % 3) * STG;
        #pragma unroll
        for (int ks = 0; ks < 2; ks++) {
            const int kb = ks * 16;
            uint32_t af[4][4], bf[4][2];
            #pragma unroll
            for (int im = 0; im < 4; im++) {
                const __half* p = sa + (wm + im * 16 + g) * ROWP + kb + 2 * c;
                af[im][0] = *(const uint32_t*)p;
                af[im][1] = *(const uint32_t*)(p + 8 * ROWP);
                af[im][2] = *(const uint32_t*)(p + 8);
                af[im][3] = *(const uint32_t*)(p + 8 * ROWP + 8);
            }
            #pragma unroll
            for (int in = 0; in < 4; in++) {
                const __half* p = sb + (wn + in * 8 + g) * ROWP + kb + 2 * c;
                bf[in][0] = *(const uint32_t*)p;
                bf[in][1] = *(const uint32_t*)(p + 8);
            }
            #pragma unroll
            for (int im = 0; im < 4; im++)
                #pragma unroll
                for (int in = 0; in < 4; in++)
                    MMA16816(acc[im][in], af[im][0], af[im][1], af[im][2], af[im][3],
                             bf[in][0], bf[in][1]);
        }
    }

    #pragma unroll
    for (int im = 0; im < 4; im++)
        #pragma unroll
        for (int in = 0; in < 4; in++) {
            const int col = bn + wn + in * 8 + 2 * c;
            if (col < Ncols) {
                const int r0 = bm + wm + im * 16 + g;
                if (Ch) {
                    *(__half2*)&Ch[(size_t)r0 * Ncols + col] =
                        __floats2half2_rn(acc[im][in][0], acc[im][in][1]);
                    *(__half2*)&Ch[(size_t)(r0 + 8) * Ncols + col] =
                        __floats2half2_rn(acc[im][in][2], acc[im][in][3]);
                } else {
                    float2 v0 = make_float2(acc[im][in][0], acc[im][in][1]);
                    float2 v1 = make_float2(acc[im][in][2], acc[im][in][3]);
                    const float2 a0 = *(const float2*)(Res + (size_t)r0 * Ncols + col);
                    const float2 a1 = *(const float2*)(Res + (size_t)(r0 + 8) * Ncols + col);
                    v0.x += a0.x; v0.y += a0.y; v1.x += a1.x; v1.y += a1.y;
                    *(float2*)(C + (size_t)r0 * Ncols + col) = v0;
                    *(float2*)(C + (size_t)(r0 + 8) * Ncols + col) = v1;
                }
            }
        }
}

// ---------------- chunk prep ----------------
#define PREP_SMEM (5 * TILE_H * 2 + 64 * PADF * 4 + 256)

__global__ __launch_bounds__(256, 2)
void chunk_prep_kernel()
{
    extern __shared__ char smraw[];
    __half* sK  = (__half*)smraw;
    __half* sQ  = sK  + TILE_H;
    __half* sKt = sQ  + TILE_H;
    __half* sVt = sKt + TILE_H;
    __half* sG  = sVt + TILE_H;
    float*  sA  = (float*)(sG + TILE_H);
    float*  sbt = sA + 64 * PADF;

    const int bid = blockIdx.x;
    const int bh = bid >> 4, cch = bid & 15;
    const int b = bh >> 3, hh = bh & 7;
    const int tid = threadIdx.x, wid = tid >> 5, lane = tid & 31;
    const int g = lane >> 2, cq = lane & 3;
    const int tt = tid >> 2, qt = tid & 3;
    const int t0 = cch * 64;
    const size_t cbase = (size_t)bid * 4096;

    // activations (fast exp)
    {
        const __half* rowp = g_qkvbh + (size_t)((t0 + tt) * BSZ + b) * NQKVB + hh * (3 * D + 1);
        if (qt == 0) sbt[tt] = 1.f / (1.f + __expf(-__half2float(rowp[3 * D])));
        float qv[16], kv[16];
        float sq = 0.f, sk_ = 0.f;
        #pragma unroll
        for (int i = 0; i < 16; i++) {
            float xq = __half2float(rowp[qt * 16 + i]);
            float xk = __half2float(rowp[D + qt * 16 + i]);
            qv[i] = xq > 0.f ? xq + 1.f : __expf(xq);
            kv[i] = xk > 0.f ? xk + 1.f : __expf(xk);
            sq += qv[i]; sk_ += kv[i];
        }
        sq  += __shfl_xor_sync(~0u, sq, 1);  sq  += __shfl_xor_sync(~0u, sq, 2);
        sk_ += __shfl_xor_sync(~0u, sk_, 1); sk_ += __shfl_xor_sync(~0u, sk_, 2);
        const float iq = 1.f / sq, ik = 1.f / sk_;
        #pragma unroll
        for (int i = 0; i < 16; i++) {
            const int col = qt * 16 + i;
            __half hq = __float2half(qv[i] * iq);
            __half hk = __float2half(kv[i] * ik);
            sQ[tt * PADH + col] = hq;
            sK[tt * PADH + col] = hk;
            sKt[col * PADH + tt] = hk;
            sVt[col * PADH + tt] = rowp[2 * D + col];
        }
    }
    __syncthreads();

    const int m0 = (wid & 3) * 16, n0 = (wid >> 2) * 32;

    // A = beta_t * stril(K K^T); S = tril_incl(Q K^T)
    {
        float aA[16], aS[16];
        #pragma unroll
        for (int i = 0; i < 16; i++) { aA[i] = 0.f; aS[i] = 0.f; }
        wgemm64(sK, sK, aA, m0, n0, g, cq);
        wgemm64(sQ, sK, aS, m0, n0, g, cq);
        #pragma unroll
        for (int nf = 0; nf < 4; nf++)
            #pragma unroll
            for (int q = 0; q < 4; q++) {
                const int t = m0 + g + ((q >> 1) << 3);
                const int s = n0 + nf * 8 + 2 * cq + (q & 1);
                sA[t * PADF + s] = (s < t) ? sbt[t] * aA[nf * 4 + q] : 0.f;
                g_Sc[cbase + t * 64 + s] = __float2half((s <= t) ? aS[nf * 4 + q] : 0.f);
            }
    }
    __syncthreads();

    // M = (I+A)^{-1}, quad-parallel forward substitution (no block barriers).
    // Thread quad (4 threads) owns column `col`; quad-lane qr owns rows [16qr,16qr+16).
    {
        const int col = tid >> 2;
        const int qr  = tid & 3;
        float m[16];
        #pragma unroll
        for (int i = 0; i < 16; i++) m[i] = (16 * qr + i == col) ? 1.f : 0.f;
        for (int p = 0; p < 4; p++) {
            #pragma unroll
            for (int si = 0; si < 16; si++) {
                const int s = 16 * p + si;
                const float ms = __shfl_sync(0xFFFFFFFFu, m[si], p, 4);
                if (ms != 0.f && qr >= p && s < 63) {
                    const int lo = (qr == p) ? si : -1;
                    #pragma unroll
                    for (int i = 0; i < 16; i++)
                        if (i > lo)
                            m[i] -= sA[(16 * qr + i) * PADF + s] * ms;
                }
            }
        }
        // G[t][col] = M[t][col] * beta[col]
        const float bc = sbt[col];
        #pragma unroll
        for (int i = 0; i < 16; i++)
            sG[(16 * qr + i) * PADH + col] = __float2half(m[i] * bc);
    }
    __syncthreads();

    // E = G @ K ; U0 = G @ V
    {
        float aE[16], aU[16];
        #pragma unroll
        for (int i = 0; i < 16; i++) { aE[i] = 0.f; aU[i] = 0.f; }
        wgemm64(sG, sKt, aE, m0, n0, g, cq);
        wgemm64(sG, sVt, aU, m0, n0, g, cq);
        #pragma unroll
        for (int nf = 0; nf < 4; nf++)
            #pragma unroll
            for (int qq = 0; qq < 2; qq++) {
                const int t = m0 + g + qq * 8;
                const int col = n0 + nf * 8 + 2 * cq;
                *(__half2*)&g_Ec[cbase + t * 64 + col] =
                    __floats2half2_rn(aE[nf * 4 + qq * 2], aE[nf * 4 + qq * 2 + 1]);
                *(__half2*)&g_U0c[cbase + t * 64 + col] =
                    __floats2half2_rn(aU[nf * 4 + qq * 2], aU[nf * 4 + qq * 2 + 1]);
            }
    }
    // store Q, K^T
    {
        const int row = tid >> 2, seg = (tid & 3) * 16;
        const uint32_t* qs = (const uint32_t*)&sQ[row * PADH + seg];
        const uint32_t* ks = (const uint32_t*)&sKt[row * PADH + seg];
        uint32_t* qd = (uint32_t*)&g_Qc[cbase + row * 64 + seg];
        uint32_t* kd = (uint32_t*)&g_Ktc[cbase + row * 64 + seg];
        #pragma unroll
        for (int i = 0; i < 8; i++) { qd[i] = qs[i]; kd[i] = ks[i]; }
    }
}

// ---------------- sequential chunk scan ----------------
#define SCAN_SMEM (10 * TILE_H * 2 + 64 * 68 * 4)

__global__ __launch_bounds__(256)
void chunk_scan_kernel()
{
    extern __shared__ char smraw[];
    __half* base = (__half*)smraw;
    __half* sEb[2]  = { base,              base + 3 * TILE_H };
    __half* sKtb[2] = { base + TILE_H,     base + 4 * TILE_H };
    __half* sU0b[2] = { base + 2 * TILE_H, base + 5 * TILE_H };
    __half* sQh = base + 6 * TILE_H;
    __half* sS  = base + 7 * TILE_H;
    __half* sWh = base + 8 * TILE_H;
    __half* sUt = base + 9 * TILE_H;
    float*  sW  = (float*)(base + 10 * TILE_H);

    const int bh = blockIdx.x;
    const int b = bh >> 3, hh = bh & 7;
    const int tid = threadIdx.x, wid = tid >> 5, lane = tid & 31;
    const int g = lane >> 2, cq = lane & 3;
    const int m0 = (wid & 3) * 16, n0 = (wid >> 2) * 32;

    #pragma unroll
    for (int i = 0; i < 16; i++) {
        const int e = tid * 16 + i;
        const int r = e >> 6, c2 = e & 63;
        sW[r * 68 + c2] = 0.f;
        sWh[r * PADH + c2] = __float2half(0.f);
    }

    const size_t sb0 = (size_t)bh * NC * 4096;
    cpa_tile(sEb[0],  g_Ec  + sb0, tid);
    cpa_tile(sKtb[0], g_Ktc + sb0, tid);
    cpa_tile(sU0b[0], g_U0c + sb0, tid);
    CP_COMMIT();
    cpa_tile(sQh, g_Qc + sb0, tid);
    cpa_tile(sS,  g_Sc + sb0, tid);
    CP_COMMIT();

    for (int cch = 0; cch < NC; cch++) {
        const int cur = cch & 1, nxt = cur ^ 1;
        CP_WAIT(1);
        __syncthreads();
        if (cch + 1 < NC) {
            const size_t sbn = sb0 + (size_t)(cch + 1) * 4096;
            cpa_tile(sEb[nxt],  g_Ec  + sbn, tid);
            cpa_tile(sKtb[nxt], g_Ktc + sbn, tid);
            cpa_tile(sU0b[nxt], g_U0c + sbn, tid);
        }
        CP_COMMIT();

        float ua[16];
        #pragma unroll
        for (int i = 0; i < 16; i++) ua[i] = 0.f;
        wgemm64(sEb[cur], sWh, ua, m0, n0, g, cq);

        CP_WAIT(1);
        __syncthreads();

        #pragma unroll
        for (int nf = 0; nf < 4; nf++)
            #pragma unroll
            for (int qq = 0; qq < 2; qq++) {
                const int t = m0 + g + qq * 8;
                const int col = n0 + nf * 8 + 2 * cq;
                const __half2 u0 = *(const __half2*)&sU0b[cur][t * PADH + col];
                sUt[col * PADH + t]       = __float2half(__half2float(u0.x) - ua[nf * 4 + qq * 2]);
                sUt[(col + 1) * PADH + t] = __float2half(__half2float(u0.y) - ua[nf * 4 + qq * 2 + 1]);
            }

        float oa[16];
        #pragma unroll
        for (int i = 0; i < 16; i++) oa[i] = 0.f;
        wgemm64(sQh, sWh, oa, m0, n0, g, cq);
        __syncthreads();

        wgemm64(sS, sUt, oa, m0, n0, g, cq);

        #pragma unroll
        for (int nf = 0; nf < 4; nf++)
            #pragma unroll
            for (int qq = 0; qq < 2; qq++) {
                const int t = m0 + g + qq * 8;
                const int col = n0 + nf * 8 + 2 * cq;
                const size_t orow = (size_t)((cch * 64 + t) * BSZ + b) * INDIM + hh * D + col;
                *(__half2*)&g_oh[orow] =
                    __floats2half2_rn(oa[nf * 4 + qq * 2], oa[nf * 4 + qq * 2 + 1]);
            }

        float wa[16];
        #pragma unroll
        for (int i = 0; i < 16; i++) wa[i] = 0.f;
        wgemm64(sUt, sKtb[cur], wa, m0, n0, g, cq);
        #pragma unroll
        for (int nf = 0; nf < 4; nf++)
            #pragma unroll
            for (int q = 0; q < 4; q++) {
                const int i = m0 + g + ((q >> 1) << 3);
                const int j = n0 + nf * 8 + 2 * cq + (q & 1);
                const float w = sW[i * 68 + j] + wa[nf * 4 + q];
                sW[i * 68 + j] = w;
                sWh[i * PADH + j] = __float2half(w);
            }
        __syncthreads();
        if (cch + 1 < NC) {
            const size_t sbn = sb0 + (size_t)(cch + 1) * 4096;
            cpa_tile(sQh, g_Qc + sbn, tid);
            cpa_tile(sS,  g_Sc + sbn, tid);
        }
        CP_COMMIT();
    }
}

// ---------------- launch ----------------
extern "C" void kernel_launch(void* const* d_in, const int* in_sizes, int n_in,
                              void* d_out, int out_size)
{
    const float* x      = (const float*)d_in[0];
    const float* gamma  = (const float*)d_in[1];
    const float* beta   = (const float*)d_in[2];
    const float* w_slow = (const float*)d_in[3];
    const float* w_out  = (const float*)d_in[4];
    float* out = (float*)d_out;

    static bool attr_set = false;
    if (!attr_set) {
        cudaFuncSetAttribute(gemm_hmma_kernel, cudaFuncAttributeMaxDynamicSharedMemorySize, GEMM_SMEM);
        cudaFuncSetAttribute(chunk_prep_kernel, cudaFuncAttributeMaxDynamicSharedMemorySize, PREP_SMEM);
        cudaFuncSetAttribute(chunk_scan_kernel, cudaFuncAttributeMaxDynamicSharedMemorySize, SCAN_SMEM);
        attr_set = true;
    }

    __half* wslowT; cudaGetSymbolAddress((void**)&wslowT, g_wslowT);
    __half* woutT;  cudaGetSymbolAddress((void**)&woutT,  g_woutT);
    __half* hbuf;   cudaGetSymbolAddress((void**)&hbuf,   g_hh);
    __half* qkvbh;  cudaGetSymbolAddress((void**)&qkvbh,  g_qkvbh);
    __half* obuf;   cudaGetSymbolAddress((void**)&obuf,   g_oh);

    {
        dim3 blk(256);
        dim3 g1(NQKVB_PAD / 32, INDIM / 32);
        transpose_pad_kernel<<<g1, blk>>>(w_slow, wslowT, INDIM, NQKVB, NQKVB_PAD);
        dim3 g2(INDIM / 32, INDIM / 32);
        transpose_pad_kernel<<<g2, blk>>>(w_out, woutT, INDIM, INDIM, INDIM);
    }
    ln_kernel<<<MROWS, 256>>>(x, gamma, beta);
    {
        dim3 grid(NQKVB_PAD / 128, MROWS / 128);
        gemm_hmma_kernel<<<grid, 256, GEMM_SMEM>>>(hbuf, wslowT, nullptr, qkvbh, nullptr, NQKVB);
    }
    chunk_prep_kernel<<<NCHUNKS, 256, PREP_SMEM>>>();
    chunk_scan_kernel<<<NBH, 256, SCAN_SMEM>>>();
    {
        dim3 grid(INDIM / 128, MROWS / 128);
        gemm_hmma_kernel<<<grid, 256, GEMM_SMEM>>>(obuf, woutT, out, nullptr, x, INDIM);
    }
}

// round 7
// speedup vs baseline: 1.6871x; 1.0337x over previous
#include <cuda_runtime.h>
#include <cuda_fp16.h>
#include <math.h>
#include <stdint.h>

#define SLEN 1024
#define BSZ  32
#define INDIM 512
#define H 8
#define D 64
#define NQKVB 1544
#define NQKVB_PAD 1664
#define MROWS 32768
#define NBH 256
#define NC 16
#define NCHUNKS (NBH * NC)
#define LN_EPS 1e-5f
#define PADH 72
#define PADF 65
#define TILE_H 4608

__device__ __half g_hh[(size_t)MROWS * INDIM];
__device__ __half g_qkvbh[(size_t)MROWS * NQKVB];
__device__ __half g_oh[(size_t)MROWS * INDIM];
__device__ __half g_wslowT[(size_t)NQKVB_PAD * INDIM];
__device__ __half g_woutT[(size_t)INDIM * INDIM];
__device__ __half g_Qc[(size_t)NCHUNKS * 4096];
__device__ __half g_Ktc[(size_t)NCHUNKS * 4096];
__device__ __half g_Sc[(size_t)NCHUNKS * 4096];
__device__ __half g_Ec[(size_t)NCHUNKS * 4096];
__device__ __half g_U0c[(size_t)NCHUNKS * 4096];

#define MMA16816(d, a0, a1, a2, a3, b0, b1)                                   \
    asm volatile("mma.sync.aligned.m16n8k16.row.col.f32.f16.f16.f32 "         \
        "{%0,%1,%2,%3},{%4,%5,%6,%7},{%8,%9},{%0,%1,%2,%3};"                   \
        : "+f"((d)[0]), "+f"((d)[1]), "+f"((d)[2]), "+f"((d)[3])               \
        : "r"(a0), "r"(a1), "r"(a2), "r"(a3), "r"(b0), "r"(b1))

#define LDSM4(r0, r1, r2, r3, a)                                              \
    asm volatile("ldmatrix.sync.aligned.m8n8.x4.shared.b16 {%0,%1,%2,%3}, [%4];" \
        : "=r"(r0), "=r"(r1), "=r"(r2), "=r"(r3) : "r"(a))

__device__ __forceinline__ uint32_t smem_u32(const void* p) {
    uint32_t a;
    asm("{ .reg .u64 t; cvta.to.shared.u64 t, %1; cvt.u32.u64 %0, t; }" : "=r"(a) : "l"(p));
    return a;
}

__device__ __forceinline__ void wgemm64(const __half* At, const __half* Bt,
                                        float acc[16], int m0, int n0, int g, int cq)
{
    #pragma unroll
    for (int kb = 0; kb < 64; kb += 16) {
        uint32_t a0 = *(const uint32_t*)&At[(m0 + g) * PADH + kb + 2 * cq];
        uint32_t a1 = *(const uint32_t*)&At[(m0 + 8 + g) * PADH + kb + 2 * cq];
        uint32_t a2 = *(const uint32_t*)&At[(m0 + g) * PADH + kb + 8 + 2 * cq];
        uint32_t a3 = *(const uint32_t*)&At[(m0 + 8 + g) * PADH + kb + 8 + 2 * cq];
        #pragma unroll
        for (int nf = 0; nf < 4; nf++) {
            uint32_t b0 = *(const uint32_t*)&Bt[(n0 + nf * 8 + g) * PADH + kb + 2 * cq];
            uint32_t b1 = *(const uint32_t*)&Bt[(n0 + nf * 8 + g) * PADH + kb + 8 + 2 * cq];
            MMA16816(&acc[nf * 4], a0, a1, a2, a3, b0, b1);
        }
    }
}

#define CP_COMMIT() asm volatile("cp.async.commit_group;")
#define CP_WAIT(n)  asm volatile("cp.async.wait_group %0;" :: "n"(n))

__device__ __forceinline__ void cpa_tile(__half* dst, const __half* src, int tid)
{
    #pragma unroll
    for (int i = 0; i < 2; i++) {
        int ch = tid + i * 256;
        int row = ch >> 3, off = (ch & 7) << 3;
        uint32_t d;
        asm("{ .reg .u64 t; cvta.to.shared.u64 t, %1; cvt.u32.u64 %0, t; }"
            : "=r"(d) : "l"(dst + row * PADH + off));
        asm volatile("cp.async.cg.shared.global [%0], [%1], 16;"
                     :: "r"(d), "l"(src + row * 64 + off));
    }
}

// ---------------- weight transpose ----------------
__global__ __launch_bounds__(256)
void transpose_pad_kernel(const float* __restrict__ src, __half* __restrict__ dst,
                          int K, int N, int Npad)
{
    __shared__ float tile[32][33];
    const int n0 = blockIdx.x * 32, k0 = blockIdx.y * 32;
    const int tx = threadIdx.x & 31, ty = threadIdx.x >> 5;
    #pragma unroll
    for (int i = ty; i < 32; i += 8) {
        const int n = n0 + tx;
        tile[i][tx] = (n < N) ? src[(size_t)(k0 + i) * N + n] : 0.f;
    }
    __syncthreads();
    #pragma unroll
    for (int i = ty; i < 32; i += 8) {
        const int n = n0 + i;
        if (n < Npad) dst[(size_t)n * K + k0 + tx] = __float2half(tile[tx][i]);
    }
}

// ---------------- LayerNorm, warp-per-row (no block barriers) ----------------
__global__ __launch_bounds__(256)
void ln_kernel(const float* __restrict__ x, const float* __restrict__ gamma,
               const float* __restrict__ beta)
{
    const int w = threadIdx.x >> 5, lane = threadIdx.x & 31;
    const int r = blockIdx.x * 8 + w;
    const float* xr = x + (size_t)r * INDIM;

    float4 v[4];
    float s = 0.f, ss = 0.f;
    #pragma unroll
    for (int i = 0; i < 4; i++) {
        v[i] = *(const float4*)(xr + lane * 4 + i * 128);
        s  += v[i].x + v[i].y + v[i].z + v[i].w;
        ss += v[i].x * v[i].x + v[i].y * v[i].y + v[i].z * v[i].z + v[i].w * v[i].w;
    }
    #pragma unroll
    for (int o = 16; o; o >>= 1) {
        s  += __shfl_xor_sync(~0u, s, o);
        ss += __shfl_xor_sync(~0u, ss, o);
    }
    const float mu = s * (1.f / INDIM);
    const float inv = rsqrtf(ss * (1.f / INDIM) - mu * mu + LN_EPS);

    __half* hr = g_hh + (size_t)r * INDIM;
    #pragma unroll
    for (int i = 0; i < 4; i++) {
        const int c0 = lane * 4 + i * 128;
        const float4 gm = *(const float4*)(gamma + c0);
        const float4 bt = *(const float4*)(beta + c0);
        __half2 h0 = __floats2half2_rn((v[i].x - mu) * inv * gm.x + bt.x,
                                       (v[i].y - mu) * inv * gm.y + bt.y);
        __half2 h1 = __floats2half2_rn((v[i].z - mu) * inv * gm.z + bt.z,
                                       (v[i].w - mu) * inv * gm.w + bt.w);
        *(uint2*)(hr + c0) = make_uint2(*(uint32_t*)&h0, *(uint32_t*)&h1);
    }
}

// ---------------- big GEMM (ldmatrix fragment loads) ----------------
#define BK 32
#define KT (INDIM / BK)
#define ROWP 40
#define STG (128 * ROWP)
#define GEMM_SMEM (3 * 2 * STG * 2)

__device__ __forceinline__ void load_stage(__half* sm, const __half* __restrict__ g,
                                           int row0, int k0, int tid)
{
    #pragma unroll
    for (int i = 0; i < 2; i++) {
        const int idx = tid + i * 256;
        const int row = idx >> 2, ch = (idx & 3) << 3;
        uint32_t dst;
        asm("{ .reg .u64 t; cvta.to.shared.u64 t, %1; cvt.u32.u64 %0, t; }"
            : "=r"(dst) : "l"(sm + row * ROWP + ch));
        asm volatile("cp.async.cg.shared.global [%0], [%1], 16;"
                     :: "r"(dst), "l"(g + (size_t)(row0 + row) * INDIM + (k0 + ch)));
    }
}

__global__ __launch_bounds__(256)
void gemm_hmma_kernel(const __half* __restrict__ A, const __half* __restrict__ Bt,
                      float* __restrict__ C, __half* __restrict__ Ch,
                      const float* __restrict__ Res, int Ncols)
{
    extern __shared__ __half sm[];
    const uint32_t smb = smem_u32(sm);
    const int tid = threadIdx.x, wid = tid >> 5, lane = tid & 31;
    const int bm = blockIdx.y * 128, bn = blockIdx.x * 128;
    const int wm = (wid >> 2) * 64, wn = (wid & 3) * 32;
    const int g = lane >> 2, c = lane & 3;
    // ldmatrix per-lane source row/col offsets
    const int rA = (lane & 7) + ((lane >> 3) & 1) * 8;
    const int cA = ((lane >> 4) & 1) * 8;
    const int rB = (lane & 7) + ((lane >> 4) & 1) * 8;
    const int cB = ((lane >> 3) & 1) * 8;

    float acc[4][4][4];
    #pragma unroll
    for (int i = 0; i < 4; i++)
        #pragma unroll
        for (int j = 0; j < 4; j++)
            #pragma unroll
            for (int r = 0; r < 4; r++) acc[i][j][r] = 0.f;

    load_stage(sm, A, bm, 0, tid); load_stage(sm + 3 * STG, Bt, bn, 0, tid); CP_COMMIT();
    load_stage(sm + STG, A, bm, BK, tid); load_stage(sm + 4 * STG, Bt, bn, BK, tid); CP_COMMIT();

    for (int kt = 0; kt < KT; ++kt) {
        CP_WAIT(1);
        __syncthreads();
        if (kt + 2 < KT) {
            const int ps = (kt + 2) % 3;
            load_stage(sm + ps * STG, A, bm, (kt + 2) * BK, tid);
            load_stage(sm + (3 + ps) * STG, Bt, bn, (kt + 2) * BK, tid);
        }
        CP_COMMIT();
        const uint32_t sau = smb + ((kt % 3) * STG) * 2;
        const uint32_t sbu = smb + ((3 + kt % 3) * STG) * 2;
        #pragma unroll
        for (int ks = 0; ks < 2; ks++) {
            const int kb = ks * 16;
            uint32_t af[4][4], bf[4][2];
            #pragma unroll
            for (int im = 0; im < 4; im++)
                LDSM4(af[im][0], af[im][1], af[im][2], af[im][3],
                      sau + ((wm + im * 16 + rA) * ROWP + kb + cA) * 2);
            #pragma unroll
            for (int i2 = 0; i2 < 2; i2++)
                LDSM4(bf[2 * i2][0], bf[2 * i2][1], bf[2 * i2 + 1][0], bf[2 * i2 + 1][1],
                      sbu + ((wn + i2 * 16 + rB) * ROWP + kb + cB) * 2);
            #pragma unroll
            for (int im = 0; im < 4; im++)
                #pragma unroll
                for (int in = 0; in < 4; in++)
                    MMA16816(acc[im][in], af[im][0], af[im][1], af[im][2], af[im][3],
                             bf[in][0], bf[in][1]);
        }
    }

    #pragma unroll
    for (int im = 0; im < 4; im++)
        #pragma unroll
        for (int in = 0; in < 4; in++) {
            const int col = bn + wn + in * 8 + 2 * c;
            if (col < Ncols) {
                const int r0 = bm + wm + im * 16 + g;
                if (Ch) {
                    *(__half2*)&Ch[(size_t)r0 * Ncols + col] =
                        __floats2half2_rn(acc[im][in][0], acc[im][in][1]);
                    *(__half2*)&Ch[(size_t)(r0 + 8) * Ncols + col] =
                        __floats2half2_rn(acc[im][in][2], acc[im][in][3]);
                } else {
                    float2 v0 = make_float2(acc[im][in][0], acc[im][in][1]);
                    float2 v1 = make_float2(acc[im][in][2], acc[im][in][3]);
                    const float2 a0 = *(const float2*)(Res + (size_t)r0 * Ncols + col);
                    const float2 a1 = *(const float2*)(Res + (size_t)(r0 + 8) * Ncols + col);
                    v0.x += a0.x; v0.y += a0.y; v1.x += a1.x; v1.y += a1.y;
                    *(float2*)(C + (size_t)r0 * Ncols + col) = v0;
                    *(float2*)(C + (size_t)(r0 + 8) * Ncols + col) = v1;
                }
            }
        }
}

// ---------------- chunk prep ----------------
#define PREP_SMEM (5 * TILE_H * 2 + 64 * PADF * 4 + 256)

__global__ __launch_bounds__(256, 2)
void chunk_prep_kernel()
{
    extern __shared__ char smraw[];
    __half* sK  = (__half*)smraw;
    __half* sQ  = sK  + TILE_H;
    __half* sKt = sQ  + TILE_H;
    __half* sVt = sKt + TILE_H;
    __half* sG  = sVt + TILE_H;
    float*  sA  = (float*)(sG + TILE_H);
    float*  sbt = sA + 64 * PADF;

    const int bid = blockIdx.x;
    const int bh = bid >> 4, cch = bid & 15;
    const int b = bh >> 3, hh = bh & 7;
    const int tid = threadIdx.x, wid = tid >> 5, lane = tid & 31;
    const int g = lane >> 2, cq = lane & 3;
    const int tt = tid >> 2, qt = tid & 3;
    const int t0 = cch * 64;
    const size_t cbase = (size_t)bid * 4096;

    {
        const __half* rowp = g_qkvbh + (size_t)((t0 + tt) * BSZ + b) * NQKVB + hh * (3 * D + 1);
        if (qt == 0) sbt[tt] = 1.f / (1.f + __expf(-__half2float(rowp[3 * D])));
        float qv[16], kv[16];
        float sq = 0.f, sk_ = 0.f;
        #pragma unroll
        for (int i = 0; i < 16; i++) {
            float xq = __half2float(rowp[qt * 16 + i]);
            float xk = __half2float(rowp[D + qt * 16 + i]);
            qv[i] = xq > 0.f ? xq + 1.f : __expf(xq);
            kv[i] = xk > 0.f ? xk + 1.f : __expf(xk);
            sq += qv[i]; sk_ += kv[i];
        }
        sq  += __shfl_xor_sync(~0u, sq, 1);  sq  += __shfl_xor_sync(~0u, sq, 2);
        sk_ += __shfl_xor_sync(~0u, sk_, 1); sk_ += __shfl_xor_sync(~0u, sk_, 2);
        const float iq = 1.f / sq, ik = 1.f / sk_;
        #pragma unroll
        for (int i = 0; i < 16; i++) {
            const int col = qt * 16 + i;
            __half hq = __float2half(qv[i] * iq);
            __half hk = __float2half(kv[i] * ik);
            sQ[tt * PADH + col] = hq;
            sK[tt * PADH + col] = hk;
            sKt[col * PADH + tt] = hk;
            sVt[col * PADH + tt] = rowp[2 * D + col];
        }
    }
    __syncthreads();

    const int m0 = (wid & 3) * 16, n0 = (wid >> 2) * 32;

    {
        float aA[16], aS[16];
        #pragma unroll
        for (int i = 0; i < 16; i++) { aA[i] = 0.f; aS[i] = 0.f; }
        wgemm64(sK, sK, aA, m0, n0, g, cq);
        wgemm64(sQ, sK, aS, m0, n0, g, cq);
        #pragma unroll
        for (int nf = 0; nf < 4; nf++)
            #pragma unroll
            for (int q = 0; q < 4; q++) {
                const int t = m0 + g + ((q >> 1) << 3);
                const int s = n0 + nf * 8 + 2 * cq + (q & 1);
                sA[t * PADF + s] = (s < t) ? sbt[t] * aA[nf * 4 + q] : 0.f;
                g_Sc[cbase + t * 64 + s] = __float2half((s <= t) ? aS[nf * 4 + q] : 0.f);
            }
    }
    __syncthreads();

    // M = (I+A)^{-1}, quad-parallel forward substitution
    {
        const int col = tid >> 2;
        const int qr  = tid & 3;
        float m[16];
        #pragma unroll
        for (int i = 0; i < 16; i++) m[i] = (16 * qr + i == col) ? 1.f : 0.f;
        for (int p = 0; p < 4; p++) {
            #pragma unroll
            for (int si = 0; si < 16; si++) {
                const int s = 16 * p + si;
                const float ms = __shfl_sync(0xFFFFFFFFu, m[si], p, 4);
                if (ms != 0.f && qr >= p && s < 63) {
                    const int lo = (qr == p) ? si : -1;
                    #pragma unroll
                    for (int i = 0; i < 16; i++)
                        if (i > lo)
                            m[i] -= sA[(16 * qr + i) * PADF + s] * ms;
                }
            }
        }
        const float bc = sbt[col];
        #pragma unroll
        for (int i = 0; i < 16; i++)
            sG[(16 * qr + i) * PADH + col] = __float2half(m[i] * bc);
    }
    __syncthreads();

    {
        float aE[16], aU[16];
        #pragma unroll
        for (int i = 0; i < 16; i++) { aE[i] = 0.f; aU[i] = 0.f; }
        wgemm64(sG, sKt, aE, m0, n0, g, cq);
        wgemm64(sG, sVt, aU, m0, n0, g, cq);
        #pragma unroll
        for (int nf = 0; nf < 4; nf++)
            #pragma unroll
            for (int qq = 0; qq < 2; qq++) {
                const int t = m0 + g + qq * 8;
                const int col = n0 + nf * 8 + 2 * cq;
                *(__half2*)&g_Ec[cbase + t * 64 + col] =
                    __floats2half2_rn(aE[nf * 4 + qq * 2], aE[nf * 4 + qq * 2 + 1]);
                *(__half2*)&g_U0c[cbase + t * 64 + col] =
                    __floats2half2_rn(aU[nf * 4 + qq * 2], aU[nf * 4 + qq * 2 + 1]);
            }
    }
    {
        const int row = tid >> 2, seg = (tid & 3) * 16;
        const uint32_t* qs = (const uint32_t*)&sQ[row * PADH + seg];
        const uint32_t* ks = (const uint32_t*)&sKt[row * PADH + seg];
        uint32_t* qd = (uint32_t*)&g_Qc[cbase + row * 64 + seg];
        uint32_t* kd = (uint32_t*)&g_Ktc[cbase + row * 64 + seg];
        #pragma unroll
        for (int i = 0; i < 8; i++) { qd[i] = qs[i]; kd[i] = ks[i]; }
    }
}

// ---------------- sequential chunk scan ----------------
#define SCAN_SMEM (10 * TILE_H * 2 + 64 * 68 * 4)

__global__ __launch_bounds__(256)
void chunk_scan_kernel()
{
    extern __shared__ char smraw[];
    __half* base = (__half*)smraw;
    __half* sEb[2]  = { base,              base + 3 * TILE_H };
    __half* sKtb[2] = { base + TILE_H,     base + 4 * TILE_H };
    __half* sU0b[2] = { base + 2 * TILE_H, base + 5 * TILE_H };
    __half* sQh = base + 6 * TILE_H;
    __half* sS  = base + 7 * TILE_H;
    __half* sWh = base + 8 * TILE_H;
    __half* sUt = base + 9 * TILE_H;
    float*  sW  = (float*)(base + 10 * TILE_H);

    const int bh = blockIdx.x;
    const int b = bh >> 3, hh = bh & 7;
    const int tid = threadIdx.x, wid = tid >> 5, lane = tid & 31;
    const int g = lane >> 2, cq = lane & 3;
    const int m0 = (wid & 3) * 16, n0 = (wid >> 2) * 32;

    #pragma unroll
    for (int i = 0; i < 16; i++) {
        const int e = tid * 16 + i;
        const int r = e >> 6, c2 = e & 63;
        sW[r * 68 + c2] = 0.f;
        sWh[r * PADH + c2] = __float2half(0.f);
    }

    const size_t sb0 = (size_t)bh * NC * 4096;
    cpa_tile(sEb[0],  g_Ec  + sb0, tid);
    cpa_tile(sKtb[0], g_Ktc + sb0, tid);
    cpa_tile(sU0b[0], g_U0c + sb0, tid);
    CP_COMMIT();
    cpa_tile(sQh, g_Qc + sb0, tid);
    cpa_tile(sS,  g_Sc + sb0, tid);
    CP_COMMIT();

    for (int cch = 0; cch < NC; cch++) {
        const int cur = cch & 1, nxt = cur ^ 1;
        CP_WAIT(1);
        __syncthreads();
        if (cch + 1 < NC) {
            const size_t sbn = sb0 + (size_t)(cch + 1) * 4096;
            cpa_tile(sEb[nxt],  g_Ec  + sbn, tid);
            cpa_tile(sKtb[nxt], g_Ktc + sbn, tid);
            cpa_tile(sU0b[nxt], g_U0c + sbn, tid);
        }
        CP_COMMIT();

        float ua[16];
        #pragma unroll
        for (int i = 0; i < 16; i++) ua[i] = 0.f;
        wgemm64(sEb[cur], sWh, ua, m0, n0, g, cq);

        CP_WAIT(1);
        __syncthreads();

        #pragma unroll
        for (int nf = 0; nf < 4; nf++)
            #pragma unroll
            for (int qq = 0; qq < 2; qq++) {
                const int t = m0 + g + qq * 8;
                const int col = n0 + nf * 8 + 2 * cq;
                const __half2 u0 = *(const __half2*)&sU0b[cur][t * PADH + col];
                sUt[col * PADH + t]       = __float2half(__half2float(u0.x) - ua[nf * 4 + qq * 2]);
                sUt[(col + 1) * PADH + t] = __float2half(__half2float(u0.y) - ua[nf * 4 + qq * 2 + 1]);
            }

        float oa[16];
        #pragma unroll
        for (int i = 0; i < 16; i++) oa[i] = 0.f;
        wgemm64(sQh, sWh, oa, m0, n0, g, cq);
        __syncthreads();

        wgemm64(sS, sUt, oa, m0, n0, g, cq);

        #pragma unroll
        for (int nf = 0; nf < 4; nf++)
            #pragma unroll
            for (int qq = 0; qq < 2; qq++) {
                const int t = m0 + g + qq * 8;
                const int col = n0 + nf * 8 + 2 * cq;
                const size_t orow = (size_t)((cch * 64 + t) * BSZ + b) * INDIM + hh * D + col;
                *(__half2*)&g_oh[orow] =
                    __floats2half2_rn(oa[nf * 4 + qq * 2], oa[nf * 4 + qq * 2 + 1]);
            }

        float wa[16];
        #pragma unroll
        for (int i = 0; i < 16; i++) wa[i] = 0.f;
        wgemm64(sUt, sKtb[cur], wa, m0, n0, g, cq);
        #pragma unroll
        for (int nf = 0; nf < 4; nf++)
            #pragma unroll
            for (int q = 0; q < 4; q++) {
                const int i = m0 + g + ((q >> 1) << 3);
                const int j = n0 + nf * 8 + 2 * cq + (q & 1);
                const float w = sW[i * 68 + j] + wa[nf * 4 + q];
                sW[i * 68 + j] = w;
                sWh[i * PADH + j] = __float2half(w);
            }
        __syncthreads();
        if (cch + 1 < NC) {
            const size_t sbn = sb0 + (size_t)(cch + 1) * 4096;
            cpa_tile(sQh, g_Qc + sbn, tid);
            cpa_tile(sS,  g_Sc + sbn, tid);
        }
        CP_COMMIT();
    }
}

// ---------------- launch ----------------
extern "C" void kernel_launch(void* const* d_in, const int* in_sizes, int n_in,
                              void* d_out, int out_size)
{
    const float* x      = (const float*)d_in[0];
    const float* gamma  = (const float*)d_in[1];
    const float* beta   = (const float*)d_in[2];
    const float* w_slow = (const float*)d_in[3];
    const float* w_out  = (const float*)d_in[4];
    float* out = (float*)d_out;

    static bool attr_set = false;
    if (!attr_set) {
        cudaFuncSetAttribute(gemm_hmma_kernel, cudaFuncAttributeMaxDynamicSharedMemorySize, GEMM_SMEM);
        cudaFuncSetAttribute(chunk_prep_kernel, cudaFuncAttributeMaxDynamicSharedMemorySize, PREP_SMEM);
        cudaFuncSetAttribute(chunk_scan_kernel, cudaFuncAttributeMaxDynamicSharedMemorySize, SCAN_SMEM);
        attr_set = true;
    }

    __half* wslowT; cudaGetSymbolAddress((void**)&wslowT, g_wslowT);
    __half* woutT;  cudaGetSymbolAddress((void**)&woutT,  g_woutT);
    __half* hbuf;   cudaGetSymbolAddress((void**)&hbuf,   g_hh);
    __half* qkvbh;  cudaGetSymbolAddress((void**)&qkvbh,  g_qkvbh);
    __half* obuf;   cudaGetSymbolAddress((void**)&obuf,   g_oh);

    {
        dim3 blk(256);
        dim3 g1(NQKVB_PAD / 32, INDIM / 32);
        transpose_pad_kernel<<<g1, blk>>>(w_slow, wslowT, INDIM, NQKVB, NQKVB_PAD);
        dim3 g2(INDIM / 32, INDIM / 32);
        transpose_pad_kernel<<<g2, blk>>>(w_out, woutT, INDIM, INDIM, INDIM);
    }
    ln_kernel<<<MROWS / 8, 256>>>(x, gamma, beta);
    {
        dim3 grid(NQKVB_PAD / 128, MROWS / 128);
        gemm_hmma_kernel<<<grid, 256, GEMM_SMEM>>>(hbuf, wslowT, nullptr, qkvbh, nullptr, NQKVB);
    }
    chunk_prep_kernel<<<NCHUNKS, 256, PREP_SMEM>>>();
    chunk_scan_kernel<<<NBH, 256, SCAN_SMEM>>>();
    {
        dim3 grid(INDIM / 128, MROWS / 128);
        gemm_hmma_kernel<<<grid, 256, GEMM_SMEM>>>(obuf, woutT, out, nullptr, x, INDIM);
    }
}

// round 9
// speedup vs baseline: 1.7426x; 1.0329x over previous
#include <cuda_runtime.h>
#include <cuda_fp16.h>
#include <math.h>
#include <stdint.h>

#define SLEN 1024
#define BSZ  32
#define INDIM 512
#define H 8
#define D 64
#define NQKVB 1544
#define NQKVB_PAD 1664
#define MROWS 32768
#define NBH 256
#define NC 16
#define NCHUNKS (NBH * NC)
#define LN_EPS 1e-5f
#define PADH 72
#define PADF 65
#define TILE_H 4608

__device__ __half g_hh[(size_t)MROWS * INDIM];
__device__ __half g_qkvbh[(size_t)MROWS * NQKVB_PAD];   // permuted layout: q|k|v|beta|pad
__device__ __half g_oh[(size_t)MROWS * INDIM];
__device__ __half g_wslowT[(size_t)NQKVB_PAD * INDIM];
__device__ __half g_woutT[(size_t)INDIM * INDIM];
__device__ __half g_Qc[(size_t)NCHUNKS * 4096];
__device__ __half g_Ktc[(size_t)NCHUNKS * 4096];
__device__ __half g_Sc[(size_t)NCHUNKS * 4096];
__device__ __half g_Ec[(size_t)NCHUNKS * 4096];
__device__ __half g_U0c[(size_t)NCHUNKS * 4096];

#define MMA16816(d, a0, a1, a2, a3, b0, b1)                                   \
    asm volatile("mma.sync.aligned.m16n8k16.row.col.f32.f16.f16.f32 "         \
        "{%0,%1,%2,%3},{%4,%5,%6,%7},{%8,%9},{%0,%1,%2,%3};"                   \
        : "+f"((d)[0]), "+f"((d)[1]), "+f"((d)[2]), "+f"((d)[3])               \
        : "r"(a0), "r"(a1), "r"(a2), "r"(a3), "r"(b0), "r"(b1))

#define LDSM4(r0, r1, r2, r3, a)                                              \
    asm volatile("ldmatrix.sync.aligned.m8n8.x4.shared.b16 {%0,%1,%2,%3}, [%4];" \
        : "=r"(r0), "=r"(r1), "=r"(r2), "=r"(r3) : "r"(a))

__device__ __forceinline__ uint32_t smem_u32(const void* p) {
    uint32_t a;
    asm("{ .reg .u64 t; cvta.to.shared.u64 t, %1; cvt.u32.u64 %0, t; }" : "=r"(a) : "l"(p));
    return a;
}

__device__ __forceinline__ void wgemm64(const __half* At, const __half* Bt,
                                        float acc[16], int m0, int n0, int g, int cq)
{
    #pragma unroll
    for (int kb = 0; kb < 64; kb += 16) {
        uint32_t a0 = *(const uint32_t*)&At[(m0 + g) * PADH + kb + 2 * cq];
        uint32_t a1 = *(const uint32_t*)&At[(m0 + 8 + g) * PADH + kb + 2 * cq];
        uint32_t a2 = *(const uint32_t*)&At[(m0 + g) * PADH + kb + 8 + 2 * cq];
        uint32_t a3 = *(const uint32_t*)&At[(m0 + 8 + g) * PADH + kb + 8 + 2 * cq];
        #pragma unroll
        for (int nf = 0; nf < 4; nf++) {
            uint32_t b0 = *(const uint32_t*)&Bt[(n0 + nf * 8 + g) * PADH + kb + 2 * cq];
            uint32_t b1 = *(const uint32_t*)&Bt[(n0 + nf * 8 + g) * PADH + kb + 8 + 2 * cq];
            MMA16816(&acc[nf * 4], a0, a1, a2, a3, b0, b1);
        }
    }
}

#define CP_COMMIT() asm volatile("cp.async.commit_group;")
#define CP_WAIT(n)  asm volatile("cp.async.wait_group %0;" :: "n"(n))

__device__ __forceinline__ void cpa_tile(__half* dst, const __half* src, int tid)
{
    #pragma unroll
    for (int i = 0; i < 2; i++) {
        int ch = tid + i * 256;
        int row = ch >> 3, off = (ch & 7) << 3;
        uint32_t d;
        asm("{ .reg .u64 t; cvta.to.shared.u64 t, %1; cvt.u32.u64 %0, t; }"
            : "=r"(d) : "l"(dst + row * PADH + off));
        asm volatile("cp.async.cg.shared.global [%0], [%1], 16;"
                     :: "r"(d), "l"(src + row * 64 + off));
    }
}

// ---------------- weight transpose (+optional head-split permutation) ----------------
__global__ __launch_bounds__(256)
void transpose_pad_kernel(const float* __restrict__ src, __half* __restrict__ dst,
                          int K, int N, int Npad, int permute)
{
    __shared__ float tile[32][33];
    const int n0 = blockIdx.x * 32, k0 = blockIdx.y * 32;
    const int tx = threadIdx.x & 31, ty = threadIdx.x >> 5;
    #pragma unroll
    for (int i = ty; i < 32; i += 8) {
        const int n = n0 + tx;
        tile[i][tx] = (n < N) ? src[(size_t)(k0 + i) * N + n] : 0.f;
    }
    __syncthreads();
    #pragma unroll
    for (int i = ty; i < 32; i += 8) {
        int n = n0 + i;
        if (n < Npad) {
            int nd = n;
            if (permute && n < N) {
                const int h = n / 193, r = n % 193;
                nd = (r < 64)  ? h * 64 + r
                   : (r < 128) ? 512 + h * 64 + (r - 64)
                   : (r < 192) ? 1024 + h * 64 + (r - 128)
                               : 1536 + h;
            }
            dst[(size_t)nd * K + k0 + tx] = __float2half(tile[tx][i]);
        }
    }
}

// ---------------- LayerNorm, warp-per-row ----------------
__global__ __launch_bounds__(256)
void ln_kernel(const float* __restrict__ x, const float* __restrict__ gamma,
               const float* __restrict__ beta)
{
    const int w = threadIdx.x >> 5, lane = threadIdx.x & 31;
    const int r = blockIdx.x * 8 + w;
    const float* xr = x + (size_t)r * INDIM;

    float4 v[4];
    float s = 0.f, ss = 0.f;
    #pragma unroll
    for (int i = 0; i < 4; i++) {
        v[i] = *(const float4*)(xr + lane * 4 + i * 128);
        s  += v[i].x + v[i].y + v[i].z + v[i].w;
        ss += v[i].x * v[i].x + v[i].y * v[i].y + v[i].z * v[i].z + v[i].w * v[i].w;
    }
    #pragma unroll
    for (int o = 16; o; o >>= 1) {
        s  += __shfl_xor_sync(~0u, s, o);
        ss += __shfl_xor_sync(~0u, ss, o);
    }
    const float mu = s * (1.f / INDIM);
    const float inv = rsqrtf(ss * (1.f / INDIM) - mu * mu + LN_EPS);

    __half* hr = g_hh + (size_t)r * INDIM;
    #pragma unroll
    for (int i = 0; i < 4; i++) {
        const int c0 = lane * 4 + i * 128;
        const float4 gm = *(const float4*)(gamma + c0);
        const float4 bt = *(const float4*)(beta + c0);
        __half2 h0 = __floats2half2_rn((v[i].x - mu) * inv * gm.x + bt.x,
                                       (v[i].y - mu) * inv * gm.y + bt.y);
        __half2 h1 = __floats2half2_rn((v[i].z - mu) * inv * gm.z + bt.z,
                                       (v[i].w - mu) * inv * gm.w + bt.w);
        *(uint2*)(hr + c0) = make_uint2(*(uint32_t*)&h0, *(uint32_t*)&h1);
    }
}

// ---------------- big GEMM ----------------
#define BK 32
#define KT (INDIM / BK)
#define ROWP 40
#define STG (128 * ROWP)
#define GEMM_SMEM (3 * 2 * STG * 2)

__device__ __forceinline__ void load_stage(__half* sm, const __half* __restrict__ g,
                                           int row0, int k0, int tid)
{
    #pragma unroll
    for (int i = 0; i < 2; i++) {
        const int idx = tid + i * 256;
        const int row = idx >> 2, ch = (idx & 3) << 3;
        uint32_t dst;
        asm("{ .reg .u64 t; cvta.to.shared.u64 t, %1; cvt.u32.u64 %0, t; }"
            : "=r"(dst) : "l"(sm + row * ROWP + ch));
        asm volatile("cp.async.cg.shared.global [%0], [%1], 16;"
                     :: "r"(dst), "l"(g + (size_t)(row0 + row) * INDIM + (k0 + ch)));
    }
}

__global__ __launch_bounds__(256)
void gemm_hmma_kernel(const __half* __restrict__ A, const __half* __restrict__ Bt,
                      float* __restrict__ C, __half* __restrict__ Ch,
                      const float* __restrict__ Res, int Ncols)
{
    extern __shared__ __half sm[];
    const uint32_t smb = smem_u32(sm);
    const int tid = threadIdx.x, wid = tid >> 5, lane = tid & 31;
    const int bm = blockIdx.y * 128, bn = blockIdx.x * 128;
    const int wm = (wid >> 2) * 64, wn = (wid & 3) * 32;
    const int g = lane >> 2, c = lane & 3;
    const int rA = (lane & 7) + ((lane >> 3) & 1) * 8;
    const int cA = ((lane >> 4) & 1) * 8;
    const int rB = (lane & 7) + ((lane >> 4) & 1) * 8;
    const int cB = ((lane >> 3) & 1) * 8;

    float acc[4][4][4];
    #pragma unroll
    for (int i = 0; i < 4; i++)
        #pragma unroll
        for (int j = 0; j < 4; j++)
            #pragma unroll
            for (int r = 0; r < 4; r++) acc[i][j][r] = 0.f;

    load_stage(sm, A, bm, 0, tid); load_stage(sm + 3 * STG, Bt, bn, 0, tid); CP_COMMIT();
    load_stage(sm + STG, A, bm, BK, tid); load_stage(sm + 4 * STG, Bt, bn, BK, tid); CP_COMMIT();

    for (int kt = 0; kt < KT; ++kt) {
        CP_WAIT(1);
        __syncthreads();
        if (kt + 2 < KT) {
            const int ps = (kt + 2) % 3;
            load_stage(sm + ps * STG, A, bm, (kt + 2) * BK, tid);
            load_stage(sm + (3 + ps) * STG, Bt, bn, (kt + 2) * BK, tid);
        }
        CP_COMMIT();
        const uint32_t sau = smb + ((kt % 3) * STG) * 2;
        const uint32_t sbu = smb + ((3 + kt % 3) * STG) * 2;
        #pragma unroll
        for (int ks = 0; ks < 2; ks++) {
            const int kb = ks * 16;
            uint32_t af[4][4], bf[4][2];
            #pragma unroll
            for (int im = 0; im < 4; im++)
                LDSM4(af[im][0], af[im][1], af[im][2], af[im][3],
                      sau + ((wm + im * 16 + rA) * ROWP + kb + cA) * 2);
            #pragma unroll
            for (int i2 = 0; i2 < 2; i2++)
                LDSM4(bf[2 * i2][0], bf[2 * i2][1], bf[2 * i2 + 1][0], bf[2 * i2 + 1][1],
                      sbu + ((wn + i2 * 16 + rB) * ROWP + kb + cB) * 2);
            #pragma unroll
            for (int im = 0; im < 4; im++)
                #pragma unroll
                for (int in = 0; in < 4; in++)
                    MMA16816(acc[im][in], af[im][0], af[im][1], af[im][2], af[im][3],
                             bf[in][0], bf[in][1]);
        }
    }

    #pragma unroll
    for (int im = 0; im < 4; im++)
        #pragma unroll
        for (int in = 0; in < 4; in++) {
            const int col = bn + wn + in * 8 + 2 * c;
            if (col < Ncols) {
                const int r0 = bm + wm + im * 16 + g;
                if (Ch) {
                    *(__half2*)&Ch[(size_t)r0 * Ncols + col] =
                        __floats2half2_rn(acc[im][in][0], acc[im][in][1]);
                    *(__half2*)&Ch[(size_t)(r0 + 8) * Ncols + col] =
                        __floats2half2_rn(acc[im][in][2], acc[im][in][3]);
                } else {
                    float2 v0 = make_float2(acc[im][in][0], acc[im][in][1]);
                    float2 v1 = make_float2(acc[im][in][2], acc[im][in][3]);
                    const float2 a0 = *(const float2*)(Res + (size_t)r0 * Ncols + col);
                    const float2 a1 = *(const float2*)(Res + (size_t)(r0 + 8) * Ncols + col);
                    v0.x += a0.x; v0.y += a0.y; v1.x += a1.x; v1.y += a1.y;
                    *(float2*)(C + (size_t)r0 * Ncols + col) = v0;
                    *(float2*)(C + (size_t)(r0 + 8) * Ncols + col) = v1;
                }
            }
        }
}

// ---------------- chunk prep (vectorized loads from permuted qkvb) ----------------
#define PREP_SMEM (5 * TILE_H * 2 + 64 * PADF * 4 + 256)

__global__ __launch_bounds__(256, 2)
void chunk_prep_kernel()
{
    extern __shared__ char smraw[];
    __half* sK  = (__half*)smraw;
    __half* sQ  = sK  + TILE_H;
    __half* sKt = sQ  + TILE_H;
    __half* sVt = sKt + TILE_H;
    __half* sG  = sVt + TILE_H;
    float*  sA  = (float*)(sG + TILE_H);
    float*  sbt = sA + 64 * PADF;

    const int bid = blockIdx.x;
    const int bh = bid >> 4, cch = bid & 15;
    const int b = bh >> 3, hh = bh & 7;
    const int tid = threadIdx.x, wid = tid >> 5, lane = tid & 31;
    const int g = lane >> 2, cq = lane & 3;
    const int tt = tid >> 2, qt = tid & 3;
    const int t0 = cch * 64;
    const size_t cbase = (size_t)bid * 4096;

    {
        const __half* rowp = g_qkvbh + (size_t)((t0 + tt) * BSZ + b) * NQKVB_PAD;
        if (qt == 0) sbt[tt] = 1.f / (1.f + __expf(-__half2float(rowp[1536 + hh])));
        __half hq[16], hk[16], hv[16];
        const int seg = hh * 64 + qt * 16;
        *(uint4*)&hq[0] = *(const uint4*)(rowp + seg);
        *(uint4*)&hq[8] = *(const uint4*)(rowp + seg + 8);
        *(uint4*)&hk[0] = *(const uint4*)(rowp + 512 + seg);
        *(uint4*)&hk[8] = *(const uint4*)(rowp + 512 + seg + 8);
        *(uint4*)&hv[0] = *(const uint4*)(rowp + 1024 + seg);
        *(uint4*)&hv[8] = *(const uint4*)(rowp + 1024 + seg + 8);

        float qv[16], kv[16];
        float sq = 0.f, sk_ = 0.f;
        #pragma unroll
        for (int i = 0; i < 16; i++) {
            float xq = __half2float(hq[i]);
            float xk = __half2float(hk[i]);
            qv[i] = xq > 0.f ? xq + 1.f : __expf(xq);
            kv[i] = xk > 0.f ? xk + 1.f : __expf(xk);
            sq += qv[i]; sk_ += kv[i];
        }
        sq  += __shfl_xor_sync(~0u, sq, 1);  sq  += __shfl_xor_sync(~0u, sq, 2);
        sk_ += __shfl_xor_sync(~0u, sk_, 1); sk_ += __shfl_xor_sync(~0u, sk_, 2);
        const float iq = 1.f / sq, ik = 1.f / sk_;
        #pragma unroll
        for (int i = 0; i < 16; i++) {
            const int col = qt * 16 + i;
            __half hqv = __float2half(qv[i] * iq);
            __half hkv = __float2half(kv[i] * ik);
            sQ[tt * PADH + col] = hqv;
            sK[tt * PADH + col] = hkv;
            sKt[col * PADH + tt] = hkv;
            sVt[col * PADH + tt] = hv[i];
        }
    }
    __syncthreads();

    const int m0 = (wid & 3) * 16, n0 = (wid >> 2) * 32;

    {
        float aA[16], aS[16];
        #pragma unroll
        for (int i = 0; i < 16; i++) { aA[i] = 0.f; aS[i] = 0.f; }
        wgemm64(sK, sK, aA, m0, n0, g, cq);
        wgemm64(sQ, sK, aS, m0, n0, g, cq);
        #pragma unroll
        for (int nf = 0; nf < 4; nf++)
            #pragma unroll
            for (int q = 0; q < 4; q++) {
                const int t = m0 + g + ((q >> 1) << 3);
                const int s = n0 + nf * 8 + 2 * cq + (q & 1);
                sA[t * PADF + s] = (s < t) ? sbt[t] * aA[nf * 4 + q] : 0.f;
                g_Sc[cbase + t * 64 + s] = __float2half((s <= t) ? aS[nf * 4 + q] : 0.f);
            }
    }
    __syncthreads();

    // M = (I+A)^{-1}, quad-parallel forward substitution
    {
        const int col = tid >> 2;
        const int qr  = tid & 3;
        float m[16];
        #pragma unroll
        for (int i = 0; i < 16; i++) m[i] = (16 * qr + i == col) ? 1.f : 0.f;
        for (int p = 0; p < 4; p++) {
            #pragma unroll
            for (int si = 0; si < 16; si++) {
                const int s = 16 * p + si;
                const float ms = __shfl_sync(0xFFFFFFFFu, m[si], p, 4);
                if (ms != 0.f && qr >= p && s < 63) {
                    const int lo = (qr == p) ? si : -1;
                    #pragma unroll
                    for (int i = 0; i < 16; i++)
                        if (i > lo)
                            m[i] -= sA[(16 * qr + i) * PADF + s] * ms;
                }
            }
        }
        const float bc = sbt[col];
        #pragma unroll
        for (int i = 0; i < 16; i++)
            sG[(16 * qr + i) * PADH + col] = __float2half(m[i] * bc);
    }
    __syncthreads();

    {
        float aE[16], aU[16];
        #pragma unroll
        for (int i = 0; i < 16; i++) { aE[i] = 0.f; aU[i] = 0.f; }
        wgemm64(sG, sKt, aE, m0, n0, g, cq);
        wgemm64(sG, sVt, aU, m0, n0, g, cq);
        #pragma unroll
        for (int nf = 0; nf < 4; nf++)
            #pragma unroll
            for (int qq = 0; qq < 2; qq++) {
                const int t = m0 + g + qq * 8;
                const int col = n0 + nf * 8 + 2 * cq;
                *(__half2*)&g_Ec[cbase + t * 64 + col] =
                    __floats2half2_rn(aE[nf * 4 + qq * 2], aE[nf * 4 + qq * 2 + 1]);
                *(__half2*)&g_U0c[cbase + t * 64 + col] =
                    __floats2half2_rn(aU[nf * 4 + qq * 2], aU[nf * 4 + qq * 2 + 1]);
            }
    }
    {
        const int row = tid >> 2, seg = (tid & 3) * 16;
        const uint32_t* qs = (const uint32_t*)&sQ[row * PADH + seg];
        const uint32_t* ks = (const uint32_t*)&sKt[row * PADH + seg];
        uint32_t* qd = (uint32_t*)&g_Qc[cbase + row * 64 + seg];
        uint32_t* kd = (uint32_t*)&g_Ktc[cbase + row * 64 + seg];
        #pragma unroll
        for (int i = 0; i < 8; i++) { qd[i] = qs[i]; kd[i] = ks[i]; }
    }
}

// ---------------- sequential chunk scan ----------------
#define SCAN_SMEM (10 * TILE_H * 2 + 64 * 68 * 4)

__global__ __launch_bounds__(256)
void chunk_scan_kernel()
{
    extern __shared__ char smraw[];
    __half* base = (__half*)smraw;
    __half* sEb[2]  = { base,              base + 3 * TILE_H };
    __half* sKtb[2] = { base + TILE_H,     base + 4 * TILE_H };
    __half* sU0b[2] = { base + 2 * TILE_H, base + 5 * TILE_H };
    __half* sQh = base + 6 * TILE_H;
    __half* sS  = base + 7 * TILE_H;
    __half* sWh = base + 8 * TILE_H;
    __half* sUt = base + 9 * TILE_H;
    float*  sW  = (float*)(base + 10 * TILE_H);

    const int bh = blockIdx.x;
    const int b = bh >> 3, hh = bh & 7;
    const int tid = threadIdx.x, wid = tid >> 5, lane = tid & 31;
    const int g = lane >> 2, cq = lane & 3;
    const int m0 = (wid & 3) * 16, n0 = (wid >> 2) * 32;

    #pragma unroll
    for (int i = 0; i < 16; i++) {
        const int e = tid * 16 + i;
        const int r = e >> 6, c2 = e & 63;
        sW[r * 68 + c2] = 0.f;
        sWh[r * PADH + c2] = __float2half(0.f);
    }

    const size_t sb0 = (size_t)bh * NC * 4096;
    cpa_tile(sEb[0],  g_Ec  + sb0, tid);
    cpa_tile(sKtb[0], g_Ktc + sb0, tid);
    cpa_tile(sU0b[0], g_U0c + sb0, tid);
    CP_COMMIT();
    cpa_tile(sQh, g_Qc + sb0, tid);
    cpa_tile(sS,  g_Sc + sb0, tid);
    CP_COMMIT();

    for (int cch = 0; cch < NC; cch++) {
        const int cur = cch & 1, nxt = cur ^ 1;
        CP_WAIT(1);
        __syncthreads();
        if (cch + 1 < NC) {
            const size_t sbn = sb0 + (size_t)(cch + 1) * 4096;
            cpa_tile(sEb[nxt],  g_Ec  + sbn, tid);
            cpa_tile(sKtb[nxt], g_Ktc + sbn, tid);
            cpa_tile(sU0b[nxt], g_U0c + sbn, tid);
        }
        CP_COMMIT();

        float ua[16];
        #pragma unroll
        for (int i = 0; i < 16; i++) ua[i] = 0.f;
        wgemm64(sEb[cur], sWh, ua, m0, n0, g, cq);

        CP_WAIT(1);
        __syncthreads();

        #pragma unroll
        for (int nf = 0; nf < 4; nf++)
            #pragma unroll
            for (int qq = 0; qq < 2; qq++) {
                const int t = m0 + g + qq * 8;
                const int col = n0 + nf * 8 + 2 * cq;
                const __half2 u0 = *(const __half2*)&sU0b[cur][t * PADH + col];
                sUt[col * PADH + t]       = __float2half(__half2float(u0.x) - ua[nf * 4 + qq * 2]);
                sUt[(col + 1) * PADH + t] = __float2half(__half2float(u0.y) - ua[nf * 4 + qq * 2 + 1]);
            }

        float oa[16];
        #pragma unroll
        for (int i = 0; i < 16; i++) oa[i] = 0.f;
        wgemm64(sQh, sWh, oa, m0, n0, g, cq);
        __syncthreads();

        wgemm64(sS, sUt, oa, m0, n0, g, cq);

        #pragma unroll
        for (int nf = 0; nf < 4; nf++)
            #pragma unroll
            for (int qq = 0; qq < 2; qq++) {
                const int t = m0 + g + qq * 8;
                const int col = n0 + nf * 8 + 2 * cq;
                const size_t orow = (size_t)((cch * 64 + t) * BSZ + b) * INDIM + hh * D + col;
                *(__half2*)&g_oh[orow] =
                    __floats2half2_rn(oa[nf * 4 + qq * 2], oa[nf * 4 + qq * 2 + 1]);
            }

        float wa[16];
        #pragma unroll
        for (int i = 0; i < 16; i++) wa[i] = 0.f;
        wgemm64(sUt, sKtb[cur], wa, m0, n0, g, cq);
        #pragma unroll
        for (int nf = 0; nf < 4; nf++)
            #pragma unroll
            for (int q = 0; q < 4; q++) {
                const int i = m0 + g + ((q >> 1) << 3);
                const int j = n0 + nf * 8 + 2 * cq + (q & 1);
                const float w = sW[i * 68 + j] + wa[nf * 4 + q];
                sW[i * 68 + j] = w;
                sWh[i * PADH + j] = __float2half(w);
            }
        __syncthreads();
        if (cch + 1 < NC) {
            const size_t sbn = sb0 + (size_t)(cch + 1) * 4096;
            cpa_tile(sQh, g_Qc + sbn, tid);
            cpa_tile(sS,  g_Sc + sbn, tid);
        }
        CP_COMMIT();
    }
}

// ---------------- launch ----------------
extern "C" void kernel_launch(void* const* d_in, const int* in_sizes, int n_in,
                              void* d_out, int out_size)
{
    const float* x      = (const float*)d_in[0];
    const float* gamma  = (const float*)d_in[1];
    const float* beta   = (const float*)d_in[2];
    const float* w_slow = (const float*)d_in[3];
    const float* w_out  = (const float*)d_in[4];
    float* out = (float*)d_out;

    static bool attr_set = false;
    if (!attr_set) {
        cudaFuncSetAttribute(gemm_hmma_kernel, cudaFuncAttributeMaxDynamicSharedMemorySize, GEMM_SMEM);
        cudaFuncSetAttribute(chunk_prep_kernel, cudaFuncAttributeMaxDynamicSharedMemorySize, PREP_SMEM);
        cudaFuncSetAttribute(chunk_scan_kernel, cudaFuncAttributeMaxDynamicSharedMemorySize, SCAN_SMEM);
        attr_set = true;
    }

    __half* wslowT; cudaGetSymbolAddress((void**)&wslowT, g_wslowT);
    __half* woutT;  cudaGetSymbolAddress((void**)&woutT,  g_woutT);
    __half* hbuf;   cudaGetSymbolAddress((void**)&hbuf,   g_hh);
    __half* qkvbh;  cudaGetSymbolAddress((void**)&qkvbh,  g_qkvbh);
    __half* obuf;   cudaGetSymbolAddress((void**)&obuf,   g_oh);

    {
        dim3 blk(256);
        dim3 g1(NQKVB_PAD / 32, INDIM / 32);
        transpose_pad_kernel<<<g1, blk>>>(w_slow, wslowT, INDIM, NQKVB, NQKVB_PAD, 1);
        dim3 g2(INDIM / 32, INDIM / 32);
        transpose_pad_kernel<<<g2, blk>>>(w_out, woutT, INDIM, INDIM, INDIM, 0);
    }
    ln_kernel<<<MROWS / 8, 256>>>(x, gamma, beta);
    {
        dim3 grid(NQKVB_PAD / 128, MROWS / 128);
        gemm_hmma_kernel<<<grid, 256, GEMM_SMEM>>>(hbuf, wslowT, nullptr, qkvbh, nullptr, NQKVB_PAD);
    }
    chunk_prep_kernel<<<NCHUNKS, 256, PREP_SMEM>>>();
    chunk_scan_kernel<<<NBH, 256, SCAN_SMEM>>>();
    {
        dim3 grid(INDIM / 128, MROWS / 128);
        gemm_hmma_kernel<<<grid, 256, GEMM_SMEM>>>(obuf, woutT, out, nullptr, x, INDIM);
    }
}

// round 10
// speedup vs baseline: 2.0159x; 1.1568x over previous
#include <cuda_runtime.h>
#include <cuda_fp16.h>
#include <math.h>
#include <stdint.h>

#define SLEN 1024
#define BSZ  32
#define INDIM 512
#define H 8
#define D 64
#define NQKVB 1544
#define NQKVB_PAD 1664
#define MROWS 32768
#define NBH 256
#define NC 16
#define LN_EPS 1e-5f
#define PADH 72
#define PADF 65
#define TILE_H 4608

__device__ __half g_hh[(size_t)MROWS * INDIM];
__device__ __half g_qkvbh[(size_t)MROWS * NQKVB_PAD];   // permuted: q|k|v|beta|pad
__device__ __half g_oh[(size_t)MROWS * INDIM];
__device__ __half g_wslowT[(size_t)NQKVB_PAD * INDIM];
__device__ __half g_woutT[(size_t)INDIM * INDIM];

#define MMA16816(d, a0, a1, a2, a3, b0, b1)                                   \
    asm volatile("mma.sync.aligned.m16n8k16.row.col.f32.f16.f16.f32 "         \
        "{%0,%1,%2,%3},{%4,%5,%6,%7},{%8,%9},{%0,%1,%2,%3};"                   \
        : "+f"((d)[0]), "+f"((d)[1]), "+f"((d)[2]), "+f"((d)[3])               \
        : "r"(a0), "r"(a1), "r"(a2), "r"(a3), "r"(b0), "r"(b1))

#define LDSM4(r0, r1, r2, r3, a)                                              \
    asm volatile("ldmatrix.sync.aligned.m8n8.x4.shared.b16 {%0,%1,%2,%3}, [%4];" \
        : "=r"(r0), "=r"(r1), "=r"(r2), "=r"(r3) : "r"(a))

__device__ __forceinline__ uint32_t smem_u32(const void* p) {
    uint32_t a;
    asm("{ .reg .u64 t; cvta.to.shared.u64 t, %1; cvt.u32.u64 %0, t; }" : "=r"(a) : "l"(p));
    return a;
}

// acc[nf*4+q] += A[m0+..][k] * B[n0+..][k]^T over k=0..63 (tiles stride PADH)
__device__ __forceinline__ void wgemm64(const __half* At, const __half* Bt,
                                        float acc[16], int m0, int n0, int g, int cq)
{
    #pragma unroll
    for (int kb = 0; kb < 64; kb += 16) {
        uint32_t a0 = *(const uint32_t*)&At[(m0 + g) * PADH + kb + 2 * cq];
        uint32_t a1 = *(const uint32_t*)&At[(m0 + 8 + g) * PADH + kb + 2 * cq];
        uint32_t a2 = *(const uint32_t*)&At[(m0 + g) * PADH + kb + 8 + 2 * cq];
        uint32_t a3 = *(const uint32_t*)&At[(m0 + 8 + g) * PADH + kb + 8 + 2 * cq];
        #pragma unroll
        for (int nf = 0; nf < 4; nf++) {
            uint32_t b0 = *(const uint32_t*)&Bt[(n0 + nf * 8 + g) * PADH + kb + 2 * cq];
            uint32_t b1 = *(const uint32_t*)&Bt[(n0 + nf * 8 + g) * PADH + kb + 8 + 2 * cq];
            MMA16816(&acc[nf * 4], a0, a1, a2, a3, b0, b1);
        }
    }
}

#define CP_COMMIT() asm volatile("cp.async.commit_group;")
#define CP_WAIT(n)  asm volatile("cp.async.wait_group %0;" :: "n"(n))

// ---------------- weight transpose (+optional head-split permutation) ----------------
__global__ __launch_bounds__(256)
void transpose_pad_kernel(const float* __restrict__ src, __half* __restrict__ dst,
                          int K, int N, int Npad, int permute)
{
    __shared__ float tile[32][33];
    const int n0 = blockIdx.x * 32, k0 = blockIdx.y * 32;
    const int tx = threadIdx.x & 31, ty = threadIdx.x >> 5;
    #pragma unroll
    for (int i = ty; i < 32; i += 8) {
        const int n = n0 + tx;
        tile[i][tx] = (n < N) ? src[(size_t)(k0 + i) * N + n] : 0.f;
    }
    __syncthreads();
    #pragma unroll
    for (int i = ty; i < 32; i += 8) {
        int n = n0 + i;
        if (n < Npad) {
            int nd = n;
            if (permute && n < N) {
                const int h = n / 193, r = n % 193;
                nd = (r < 64)  ? h * 64 + r
                   : (r < 128) ? 512 + h * 64 + (r - 64)
                   : (r < 192) ? 1024 + h * 64 + (r - 128)
                               : 1536 + h;
            }
            dst[(size_t)nd * K + k0 + tx] = __float2half(tile[tx][i]);
        }
    }
}

// ---------------- LayerNorm, warp-per-row ----------------
__global__ __launch_bounds__(256)
void ln_kernel(const float* __restrict__ x, const float* __restrict__ gamma,
               const float* __restrict__ beta)
{
    const int w = threadIdx.x >> 5, lane = threadIdx.x & 31;
    const int r = blockIdx.x * 8 + w;
    const float* xr = x + (size_t)r * INDIM;

    float4 v[4];
    float s = 0.f, ss = 0.f;
    #pragma unroll
    for (int i = 0; i < 4; i++) {
        v[i] = *(const float4*)(xr + lane * 4 + i * 128);
        s  += v[i].x + v[i].y + v[i].z + v[i].w;
        ss += v[i].x * v[i].x + v[i].y * v[i].y + v[i].z * v[i].z + v[i].w * v[i].w;
    }
    #pragma unroll
    for (int o = 16; o; o >>= 1) {
        s  += __shfl_xor_sync(~0u, s, o);
        ss += __shfl_xor_sync(~0u, ss, o);
    }
    const float mu = s * (1.f / INDIM);
    const float inv = rsqrtf(ss * (1.f / INDIM) - mu * mu + LN_EPS);

    __half* hr = g_hh + (size_t)r * INDIM;
    #pragma unroll
    for (int i = 0; i < 4; i++) {
        const int c0 = lane * 4 + i * 128;
        const float4 gm = *(const float4*)(gamma + c0);
        const float4 bt = *(const float4*)(beta + c0);
        __half2 h0 = __floats2half2_rn((v[i].x - mu) * inv * gm.x + bt.x,
                                       (v[i].y - mu) * inv * gm.y + bt.y);
        __half2 h1 = __floats2half2_rn((v[i].z - mu) * inv * gm.z + bt.z,
                                       (v[i].w - mu) * inv * gm.w + bt.w);
        *(uint2*)(hr + c0) = make_uint2(*(uint32_t*)&h0, *(uint32_t*)&h1);
    }
}

// ---------------- big GEMM ----------------
#define BK 32
#define KT (INDIM / BK)
#define ROWP 40
#define STG (128 * ROWP)
#define GEMM_SMEM (3 * 2 * STG * 2)

__device__ __forceinline__ void load_stage(__half* sm, const __half* __restrict__ g,
                                           int row0, int k0, int tid)
{
    #pragma unroll
    for (int i = 0; i < 2; i++) {
        const int idx = tid + i * 256;
        const int row = idx >> 2, ch = (idx & 3) << 3;
        uint32_t dst;
        asm("{ .reg .u64 t; cvta.to.shared.u64 t, %1; cvt.u32.u64 %0, t; }"
            : "=r"(dst) : "l"(sm + row * ROWP + ch));
        asm volatile("cp.async.cg.shared.global [%0], [%1], 16;"
                     :: "r"(dst), "l"(g + (size_t)(row0 + row) * INDIM + (k0 + ch)));
    }
}

__global__ __launch_bounds__(256)
void gemm_hmma_kernel(const __half* __restrict__ A, const __half* __restrict__ Bt,
                      float* __restrict__ C, __half* __restrict__ Ch,
                      const float* __restrict__ Res, int Ncols)
{
    extern __shared__ __half sm[];
    const uint32_t smb = smem_u32(sm);
    const int tid = threadIdx.x, wid = tid >> 5, lane = tid & 31;
    const int bm = blockIdx.y * 128, bn = blockIdx.x * 128;
    const int wm = (wid >> 2) * 64, wn = (wid & 3) * 32;
    const int g = lane >> 2, c = lane & 3;
    const int rA = (lane & 7) + ((lane >> 3) & 1) * 8;
    const int cA = ((lane >> 4) & 1) * 8;
    const int rB = (lane & 7) + ((lane >> 4) & 1) * 8;
    const int cB = ((lane >> 3) & 1) * 8;

    float acc[4][4][4];
    #pragma unroll
    for (int i = 0; i < 4; i++)
        #pragma unroll
        for (int j = 0; j < 4; j++)
            #pragma unroll
            for (int r = 0; r < 4; r++) acc[i][j][r] = 0.f;

    load_stage(sm, A, bm, 0, tid); load_stage(sm + 3 * STG, Bt, bn, 0, tid); CP_COMMIT();
    load_stage(sm + STG, A, bm, BK, tid); load_stage(sm + 4 * STG, Bt, bn, BK, tid); CP_COMMIT();

    for (int kt = 0; kt < KT; ++kt) {
        CP_WAIT(1);
        __syncthreads();
        if (kt + 2 < KT) {
            const int ps = (kt + 2) % 3;
            load_stage(sm + ps * STG, A, bm, (kt + 2) * BK, tid);
            load_stage(sm + (3 + ps) * STG, Bt, bn, (kt + 2) * BK, tid);
        }
        CP_COMMIT();
        const uint32_t sau = smb + ((kt % 3) * STG) * 2;
        const uint32_t sbu = smb + ((3 + kt % 3) * STG) * 2;
        #pragma unroll
        for (int ks = 0; ks < 2; ks++) {
            const int kb = ks * 16;
            uint32_t af[4][4], bf[4][2];
            #pragma unroll
            for (int im = 0; im < 4; im++)
                LDSM4(af[im][0], af[im][1], af[im][2], af[im][3],
                      sau + ((wm + im * 16 + rA) * ROWP + kb + cA) * 2);
            #pragma unroll
            for (int i2 = 0; i2 < 2; i2++)
                LDSM4(bf[2 * i2][0], bf[2 * i2][1], bf[2 * i2 + 1][0], bf[2 * i2 + 1][1],
                      sbu + ((wn + i2 * 16 + rB) * ROWP + kb + cB) * 2);
            #pragma unroll
            for (int im = 0; im < 4; im++)
                #pragma unroll
                for (int in = 0; in < 4; in++)
                    MMA16816(acc[im][in], af[im][0], af[im][1], af[im][2], af[im][3],
                             bf[in][0], bf[in][1]);
        }
    }

    #pragma unroll
    for (int im = 0; im < 4; im++)
        #pragma unroll
        for (int in = 0; in < 4; in++) {
            const int col = bn + wn + in * 8 + 2 * c;
            if (col < Ncols) {
                const int r0 = bm + wm + im * 16 + g;
                if (Ch) {
                    *(__half2*)&Ch[(size_t)r0 * Ncols + col] =
                        __floats2half2_rn(acc[im][in][0], acc[im][in][1]);
                    *(__half2*)&Ch[(size_t)(r0 + 8) * Ncols + col] =
                        __floats2half2_rn(acc[im][in][2], acc[im][in][3]);
                } else {
                    float2 v0 = make_float2(acc[im][in][0], acc[im][in][1]);
                    float2 v1 = make_float2(acc[im][in][2], acc[im][in][3]);
                    const float2 a0 = *(const float2*)(Res + (size_t)r0 * Ncols + col);
                    const float2 a1 = *(const float2*)(Res + (size_t)(r0 + 8) * Ncols + col);
                    v0.x += a0.x; v0.y += a0.y; v1.x += a1.x; v1.y += a1.y;
                    *(float2*)(C + (size_t)r0 * Ncols + col) = v0;
                    *(float2*)(C + (size_t)(r0 + 8) * Ncols + col) = v1;
                }
            }
        }
}

// ---------------- fused chunk prep + sequential scan (256 CTAs) ----------------
// smem tiles (time-shared): T0 sK->sE, T1 sQ, T2 sKt, T3 sVt->sUt, T4 sG, T5 sS, T6 sWh
#define FUSED_SMEM (7 * TILE_H * 2 + (64 * PADF + 64 * 68 + 64) * 4)

__global__ __launch_bounds__(256, 2)
void fused_scan_kernel()
{
    extern __shared__ char smraw[];
    __half* sKE  = (__half*)smraw;
    __half* sQ   = sKE  + TILE_H;
    __half* sKt  = sQ   + TILE_H;
    __half* sVUt = sKt  + TILE_H;
    __half* sG   = sVUt + TILE_H;
    __half* sS   = sG   + TILE_H;
    __half* sWh  = sS   + TILE_H;
    float*  sA   = (float*)(sWh + TILE_H);
    float*  sW   = sA + 64 * PADF;
    float*  sbt  = sW + 64 * 68;

    const int bh = blockIdx.x;
    const int b = bh >> 3, hh = bh & 7;
    const int tid = threadIdx.x, wid = tid >> 5, lane = tid & 31;
    const int g = lane >> 2, cq = lane & 3;
    const int tt = tid >> 2, qt = tid & 3;
    const int m0 = (wid & 3) * 16, n0 = (wid >> 2) * 32;

    // W = 0
    #pragma unroll
    for (int i = 0; i < 16; i++) {
        const int e = tid * 16 + i;
        const int r = e >> 6, c2 = e & 63;
        sW[r * 68 + c2] = 0.f;
        sWh[r * PADH + c2] = __float2half(0.f);
    }
    __syncthreads();

    for (int cch = 0; cch < NC; cch++) {
        const int t0 = cch * 64;

        // ---- act: q,k,beta + transposes ----
        {
            const __half* rowp = g_qkvbh + (size_t)((t0 + tt) * BSZ + b) * NQKVB_PAD;
            if (qt == 0) sbt[tt] = 1.f / (1.f + __expf(-__half2float(rowp[1536 + hh])));
            __half hq[16], hk[16], hv[16];
            const int seg = hh * 64 + qt * 16;
            *(uint4*)&hq[0] = *(const uint4*)(rowp + seg);
            *(uint4*)&hq[8] = *(const uint4*)(rowp + seg + 8);
            *(uint4*)&hk[0] = *(const uint4*)(rowp + 512 + seg);
            *(uint4*)&hk[8] = *(const uint4*)(rowp + 512 + seg + 8);
            *(uint4*)&hv[0] = *(const uint4*)(rowp + 1024 + seg);
            *(uint4*)&hv[8] = *(const uint4*)(rowp + 1024 + seg + 8);

            float qv[16], kv[16];
            float sq = 0.f, sk_ = 0.f;
            #pragma unroll
            for (int i = 0; i < 16; i++) {
                float xq = __half2float(hq[i]);
                float xk = __half2float(hk[i]);
                qv[i] = xq > 0.f ? xq + 1.f : __expf(xq);
                kv[i] = xk > 0.f ? xk + 1.f : __expf(xk);
                sq += qv[i]; sk_ += kv[i];
            }
            sq  += __shfl_xor_sync(~0u, sq, 1);  sq  += __shfl_xor_sync(~0u, sq, 2);
            sk_ += __shfl_xor_sync(~0u, sk_, 1); sk_ += __shfl_xor_sync(~0u, sk_, 2);
            const float iq = 1.f / sq, ik = 1.f / sk_;
            #pragma unroll
            for (int i = 0; i < 16; i++) {
                const int col = qt * 16 + i;
                __half hqv = __float2half(qv[i] * iq);
                __half hkv = __float2half(kv[i] * ik);
                sQ[tt * PADH + col] = hqv;
                sKE[tt * PADH + col] = hkv;
                sKt[col * PADH + tt] = hkv;
                sVUt[col * PADH + tt] = hv[i];
            }
        }
        __syncthreads();   // (a)

        // ---- A = beta_t * stril(K K^T);  S = tril_incl(Q K^T) ----
        {
            float aA[16], aS[16];
            #pragma unroll
            for (int i = 0; i < 16; i++) { aA[i] = 0.f; aS[i] = 0.f; }
            wgemm64(sKE, sKE, aA, m0, n0, g, cq);
            wgemm64(sQ, sKE, aS, m0, n0, g, cq);
            #pragma unroll
            for (int nf = 0; nf < 4; nf++)
                #pragma unroll
                for (int q = 0; q < 4; q++) {
                    const int t = m0 + g + ((q >> 1) << 3);
                    const int s = n0 + nf * 8 + 2 * cq + (q & 1);
                    sA[t * PADF + s] = (s < t) ? sbt[t] * aA[nf * 4 + q] : 0.f;
                    sS[t * PADH + s] = __float2half((s <= t) ? aS[nf * 4 + q] : 0.f);
                }
        }
        __syncthreads();   // (b)

        // ---- M = (I+A)^{-1}, quad-parallel forward substitution; G = M diag(beta) ----
        {
            const int col = tid >> 2;
            const int qr  = tid & 3;
            float m[16];
            #pragma unroll
            for (int i = 0; i < 16; i++) m[i] = (16 * qr + i == col) ? 1.f : 0.f;
            for (int p = 0; p < 4; p++) {
                #pragma unroll
                for (int si = 0; si < 16; si++) {
                    const int s = 16 * p + si;
                    const float ms = __shfl_sync(0xFFFFFFFFu, m[si], p, 4);
                    if (ms != 0.f && qr >= p && s < 63) {
                        const int lo = (qr == p) ? si : -1;
                        #pragma unroll
                        for (int i = 0; i < 16; i++)
                            if (i > lo)
                                m[i] -= sA[(16 * qr + i) * PADF + s] * ms;
                    }
                }
            }
            const float bc = sbt[col];
            #pragma unroll
            for (int i = 0; i < 16; i++)
                sG[(16 * qr + i) * PADH + col] = __float2half(m[i] * bc);
        }
        __syncthreads();   // (c)

        // ---- E = G @ K (to sKE);  U0 = G @ V (registers) ----
        float aU[16];
        {
            float aE[16];
            #pragma unroll
            for (int i = 0; i < 16; i++) { aE[i] = 0.f; aU[i] = 0.f; }
            wgemm64(sG, sKt, aE, m0, n0, g, cq);
            wgemm64(sG, sVUt, aU, m0, n0, g, cq);
            #pragma unroll
            for (int nf = 0; nf < 4; nf++)
                #pragma unroll
                for (int qq = 0; qq < 2; qq++) {
                    const int t = m0 + g + qq * 8;
                    const int col = n0 + nf * 8 + 2 * cq;
                    *(__half2*)&sKE[t * PADH + col] =
                        __floats2half2_rn(aE[nf * 4 + qq * 2], aE[nf * 4 + qq * 2 + 1]);
                }
        }
        __syncthreads();   // (d)  [sE visible; sVt reads done]

        // ---- U = U0 - E @ W0^T (to sUt);  O1 = Q @ W0^T ----
        float oa[16];
        {
            float ua[16];
            #pragma unroll
            for (int i = 0; i < 16; i++) { ua[i] = 0.f; oa[i] = 0.f; }
            wgemm64(sKE, sWh, ua, m0, n0, g, cq);
            wgemm64(sQ, sWh, oa, m0, n0, g, cq);
            #pragma unroll
            for (int nf = 0; nf < 4; nf++)
                #pragma unroll
                for (int qq = 0; qq < 2; qq++) {
                    const int t = m0 + g + qq * 8;
                    const int col = n0 + nf * 8 + 2 * cq;
                    sVUt[col * PADH + t] =
                        __float2half(aU[nf * 4 + qq * 2] - ua[nf * 4 + qq * 2]);
                    sVUt[(col + 1) * PADH + t] =
                        __float2half(aU[nf * 4 + qq * 2 + 1] - ua[nf * 4 + qq * 2 + 1]);
                }
        }
        __syncthreads();   // (e)  [sUt visible; sWh reads done]

        // ---- O2 = S @ U; store O;  W += U^T @ K ----
        wgemm64(sS, sVUt, oa, m0, n0, g, cq);
        #pragma unroll
        for (int nf = 0; nf < 4; nf++)
            #pragma unroll
            for (int qq = 0; qq < 2; qq++) {
                const int t = m0 + g + qq * 8;
                const int col = n0 + nf * 8 + 2 * cq;
                const size_t orow = (size_t)((t0 + t) * BSZ + b) * INDIM + hh * D + col;
                *(__half2*)&g_oh[orow] =
                    __floats2half2_rn(oa[nf * 4 + qq * 2], oa[nf * 4 + qq * 2 + 1]);
            }
        {
            float wa[16];
            #pragma unroll
            for (int i = 0; i < 16; i++) wa[i] = 0.f;
            wgemm64(sVUt, sKt, wa, m0, n0, g, cq);
            #pragma unroll
            for (int nf = 0; nf < 4; nf++)
                #pragma unroll
                for (int q = 0; q < 4; q++) {
                    const int i = m0 + g + ((q >> 1) << 3);
                    const int j = n0 + nf * 8 + 2 * cq + (q & 1);
                    const float w = sW[i * 68 + j] + wa[nf * 4 + q];
                    sW[i * 68 + j] = w;
                    sWh[i * PADH + j] = __float2half(w);
                }
        }
        __syncthreads();   // (f)  [tiles free for next chunk; sWh updated]
    }
}

// ---------------- launch ----------------
extern "C" void kernel_launch(void* const* d_in, const int* in_sizes, int n_in,
                              void* d_out, int out_size)
{
    const float* x      = (const float*)d_in[0];
    const float* gamma  = (const float*)d_in[1];
    const float* beta   = (const float*)d_in[2];
    const float* w_slow = (const float*)d_in[3];
    const float* w_out  = (const float*)d_in[4];
    float* out = (float*)d_out;

    static bool attr_set = false;
    if (!attr_set) {
        cudaFuncSetAttribute(gemm_hmma_kernel, cudaFuncAttributeMaxDynamicSharedMemorySize, GEMM_SMEM);
        cudaFuncSetAttribute(fused_scan_kernel, cudaFuncAttributeMaxDynamicSharedMemorySize, FUSED_SMEM);
        attr_set = true;
    }

    __half* wslowT; cudaGetSymbolAddress((void**)&wslowT, g_wslowT);
    __half* woutT;  cudaGetSymbolAddress((void**)&woutT,  g_woutT);
    __half* hbuf;   cudaGetSymbolAddress((void**)&hbuf,   g_hh);
    __half* qkvbh;  cudaGetSymbolAddress((void**)&qkvbh,  g_qkvbh);
    __half* obuf;   cudaGetSymbolAddress((void**)&obuf,   g_oh);

    {
        dim3 blk(256);
        dim3 g1(NQKVB_PAD / 32, INDIM / 32);
        transpose_pad_kernel<<<g1, blk>>>(w_slow, wslowT, INDIM, NQKVB, NQKVB_PAD, 1);
        dim3 g2(INDIM / 32, INDIM / 32);
        transpose_pad_kernel<<<g2, blk>>>(w_out, woutT, INDIM, INDIM, INDIM, 0);
    }
    ln_kernel<<<MROWS / 8, 256>>>(x, gamma, beta);
    {
        dim3 grid(NQKVB_PAD / 128, MROWS / 128);
        gemm_hmma_kernel<<<grid, 256, GEMM_SMEM>>>(hbuf, wslowT, nullptr, qkvbh, nullptr, NQKVB_PAD);
    }
    fused_scan_kernel<<<NBH, 256, FUSED_SMEM>>>();
    {
        dim3 grid(INDIM / 128, MROWS / 128);
        gemm_hmma_kernel<<<grid, 256, GEMM_SMEM>>>(obuf, woutT, out, nullptr, x, INDIM);
    }
}